// round 14
// baseline (speedup 1.0000x reference)
#include <cuda_runtime.h>
#include <cuda_bf16.h>
#include <math.h>
#include <stdint.h>

#define Bn  32
#define LCn 2048
#define LRn 512
#define Dn  256
#define Hn  128
#define MC  (Bn * LCn)
#define MR  (Bn * LRn)
#define SHIFTC 64.0f

typedef __nv_bfloat16 bf16;

// -------- scratch --------
static __device__ bf16 g_EH [(size_t)Bn * LCn * LRn], g_EL [(size_t)Bn * LCn * LRn];
static __device__ bf16 g_csH[(size_t)Bn * LCn * Dn],  g_csL[(size_t)Bn * LCn * Dn];
static __device__ bf16 g_rsH[(size_t)Bn * LRn * Dn],  g_rsL[(size_t)Bn * LRn * Dn];
static __device__ bf16 g_csTH[(size_t)Bn * Dn * LCn], g_csTL[(size_t)Bn * Dn * LCn];
static __device__ bf16 g_rsTH[(size_t)Bn * Dn * LRn], g_rsTL[(size_t)Bn * Dn * LRn];
static __device__ bf16 g_cdH[(size_t)Bn * LCn * Dn],  g_cdL[(size_t)Bn * LCn * Dn];
static __device__ bf16 g_pcH[(size_t)Bn * LCn * Dn],  g_pcL[(size_t)Bn * LCn * Dn];
static __device__ bf16 g_rdH[(size_t)Bn * LRn * Dn],  g_rdL[(size_t)Bn * LRn * Dn];
static __device__ bf16 g_prH[(size_t)Bn * LRn * Dn],  g_prL[(size_t)Bn * LRn * Dn];
static __device__ bf16 g_W1H[Hn * 3 * Dn], g_W1L[Hn * 3 * Dn];
static __device__ bf16 g_W2H[Hn * 3 * Dn], g_W2L[Hn * 3 * Dn];
static __device__ float g_asum[MC];
static __device__ float g_bsum[MR];
static __device__ float g_prS[(size_t)Bn * 8 * LCn];     // row-sum partials
static __device__ float g_pcS[(size_t)Bn * 32 * LRn];    // col-sum partials

// ======================== helpers =============================
__device__ __forceinline__ uint32_t smem_u32(const void* p) {
    uint32_t a;
    asm("{ .reg .u64 t; cvta.to.shared.u64 t, %1; cvt.u32.u64 %0, t; }" : "=r"(a) : "l"(p));
    return a;
}

#define LDSM4(r, addr) \
    asm volatile("ldmatrix.sync.aligned.m8n8.x4.shared.b16 {%0,%1,%2,%3}, [%4];" \
        : "=r"((r)[0]), "=r"((r)[1]), "=r"((r)[2]), "=r"((r)[3]) : "r"(addr))

#define LDSM4T(r, addr) \
    asm volatile("ldmatrix.sync.aligned.m8n8.x4.trans.shared.b16 {%0,%1,%2,%3}, [%4];" \
        : "=r"((r)[0]), "=r"((r)[1]), "=r"((r)[2]), "=r"((r)[3]) : "r"(addr))

#define MMA_BF16(c, a, b0, b1) \
    asm volatile("mma.sync.aligned.m16n8k16.row.col.f32.bf16.bf16.f32 " \
        "{%0,%1,%2,%3}, {%4,%5,%6,%7}, {%8,%9}, {%0,%1,%2,%3};" \
        : "+f"((c)[0]), "+f"((c)[1]), "+f"((c)[2]), "+f"((c)[3]) \
        : "r"((a)[0]), "r"((a)[1]), "r"((a)[2]), "r"((a)[3]), "r"(b0), "r"(b1))

#define CP16(dst, src) \
    asm volatile("cp.async.cg.shared.global [%0], [%1], 16;" :: "r"(dst), "l"(src))
#define CP_COMMIT() asm volatile("cp.async.commit_group;" ::: "memory")
#define CP_WAIT(n)  asm volatile("cp.async.wait_group %0;" :: "n"(n) : "memory")

__device__ __forceinline__ void bsplit(float v, bf16& h, bf16& l) {
    h = __float2bfloat16(v);
    l = __float2bfloat16(v - __bfloat162float(h));
}

// non-trans smem tile: [rows][32 k] bf16, 64B rows; conflict-free swizzle.
__device__ __forceinline__ uint32_t toff16(int row, int u) {
    return (row << 6) + ((u ^ ((row >> 1) & 3)) << 4);
}

#define SM_AH 0
#define SM_AL 8192
#define SM_BH 16384
#define SM_BL 24576
#define STAGE_B 32768
#define SMEM_DYN (3 * STAGE_B)

// ============================================================================
// Core NT GEMM on pre-split bf16 pairs: C[128,128] = A[128,K]*B[128,K]^T
// (3 products HH+HL+LH).
// TRA=1: A operand is E^T, streamed from row-major E via ldmatrix.trans.
// EPI 0: emit exp(acc-SHIFT) split pairs + plain row/col partial sums.
// EPI 1: scale 1/rsum, emit split pairs + split(X*scaled).  EPI 2: relu+bias.
// ============================================================================
template<int EPI, int TRA>
__device__ __forceinline__ void gemm_core(
    const bf16* __restrict__ AH0, const bf16* __restrict__ AL0,
    const bf16* __restrict__ AH1, const bf16* __restrict__ AL1,
    const bf16* __restrict__ AH2, const bf16* __restrict__ AL2,
    const bf16* __restrict__ BH,  const bf16* __restrict__ BL,
    const float* __restrict__ rsum, const float* __restrict__ Xf,
    const float* __restrict__ bias, float* __restrict__ Cf,
    bf16* __restrict__ CoH, bf16* __restrict__ CoL,
    bf16* __restrict__ PoH, bf16* __restrict__ PoL,
    float* __restrict__ PrS, float* __restrict__ PcS,
    int K, int lda, int ldb, int ldc,
    size_t aB, size_t bB, size_t cB, int sB,
    int bx, int by, int bz)
{
    extern __shared__ __align__(16) uint8_t sm[];
    const uint32_t sb = smem_u32(sm);
    const int tid = threadIdx.x;
    const int z = bz;
    const int m0 = bx * 128, n0 = by * 128;
    const bf16* aH0 = AH0 + (size_t)z * aB;
    const bf16* aL0 = AL0 + (size_t)z * aB;
    const bf16* bH  = BH  + (size_t)z * bB;
    const bf16* bL  = BL  + (size_t)z * bB;

    const int lane = tid & 31, wid = tid >> 5;
    const int wm = wid & 1, wn = wid >> 1;
    const int gid = lane >> 2, tig = lane & 3;

    float acc[4][8][4];
    #pragma unroll
    for (int a = 0; a < 4; a++)
        #pragma unroll
        for (int b = 0; b < 8; b++)
            #pragma unroll
            for (int c = 0; c < 4; c++) acc[a][b][c] = 0.f;

    const int S = K >> 5;

    auto cp_stage = [&](int buf, int kc) {
        const uint32_t tb = sb + buf * STAGE_B;
        const int k0 = kc << 5;
        if (TRA) {
            #pragma unroll
            for (int i = 0; i < 4; i++) {
                int idx = tid + i * 128;
                int row = idx >> 4, u = idx & 15;
                uint32_t up = (uint32_t)(u ^ (row & 7));
                uint32_t off = row * 256 + up * 16;
                const size_t g = (size_t)(k0 + row) * lda + m0 + u * 8;
                CP16(tb + SM_AH + off, aH0 + g);
                CP16(tb + SM_AL + off, aL0 + g);
            }
        } else {
            const bf16* aH = aH0; const bf16* aL = aL0;
            int kk = k0;
            if (EPI == 2) {
                int seg = k0 >> 8; kk = k0 & 255;
                if (seg == 1) { aH = AH1; aL = AL1; }
                else if (seg == 2) { aH = AH2; aL = AL2; }
            }
            #pragma unroll
            for (int i = 0; i < 4; i++) {
                int idx = tid + i * 128;
                int row = idx >> 2, u = idx & 3;
                uint32_t off = toff16(row, u);
                const size_t g = (size_t)(m0 + row) * lda + kk + u * 8;
                CP16(tb + SM_AH + off, aH + g);
                CP16(tb + SM_AL + off, aL + g);
            }
        }
        #pragma unroll
        for (int i = 0; i < 4; i++) {
            int idx = tid + i * 128;
            int row = idx >> 2, u = idx & 3;
            uint32_t off = toff16(row, u);
            const size_t g = (size_t)(n0 + row) * ldb + k0 + u * 8;
            CP16(tb + SM_BH + off, bH + g);
            CP16(tb + SM_BL + off, bL + g);
        }
    };

    auto ldA = [&](uint32_t tb, int kb, uint32_t (&ah)[4][4], uint32_t (&al)[4][4]) {
        if (TRA) {
            int rowk = kb * 16 + ((lane >> 4) << 3) + (lane & 7);
            #pragma unroll
            for (int mb = 0; mb < 4; mb++) {
                int um = wm * 8 + mb * 2 + ((lane >> 3) & 1);
                uint32_t up = (uint32_t)(um ^ (rowk & 7));
                uint32_t addr = tb + rowk * 256 + up * 16;
                LDSM4T(ah[mb], addr + SM_AH);
                LDSM4T(al[mb], addr + SM_AL);
            }
        } else {
            #pragma unroll
            for (int mb = 0; mb < 4; mb++) {
                int row = wm * 64 + mb * 16 + (lane & 15);
                uint32_t off = toff16(row, kb * 2 + (lane >> 4));
                LDSM4(ah[mb], tb + SM_AH + off);
                LDSM4(al[mb], tb + SM_AL + off);
            }
        }
    };

    auto mmaHalf = [&](uint32_t tb, int kb, uint32_t (&ah)[4][4], uint32_t (&al)[4][4]) {
        #pragma unroll
        for (int np = 0; np < 4; np++) {
            int nrow = wn * 64 + np * 16 + (lane & 7) + ((lane >> 4) << 3);
            uint32_t off = toff16(nrow, kb * 2 + ((lane >> 3) & 1));
            uint32_t bh[4], bl[4];
            LDSM4(bh, tb + SM_BH + off);
            LDSM4(bl, tb + SM_BL + off);
            #pragma unroll
            for (int nb = 0; nb < 2; nb++)
                #pragma unroll
                for (int mb = 0; mb < 4; mb++)
                    MMA_BF16(acc[mb][np*2+nb], ah[mb], bh[nb*2], bh[nb*2+1]);
            #pragma unroll
            for (int nb = 0; nb < 2; nb++)
                #pragma unroll
                for (int mb = 0; mb < 4; mb++)
                    MMA_BF16(acc[mb][np*2+nb], ah[mb], bl[nb*2], bl[nb*2+1]);
            #pragma unroll
            for (int nb = 0; nb < 2; nb++)
                #pragma unroll
                for (int mb = 0; mb < 4; mb++)
                    MMA_BF16(acc[mb][np*2+nb], al[mb], bh[nb*2], bh[nb*2+1]);
        }
    };

    uint32_t A0h[4][4], A0l[4][4], A1h[4][4], A1l[4][4];

    cp_stage(0, 0); CP_COMMIT();
    if (S > 1) cp_stage(1, 1);
    CP_COMMIT();
    CP_WAIT(1);
    __syncthreads();
    ldA(sb, 0, A0h, A0l);

    for (int s = 0; s < S; s++) {
        const uint32_t tb = sb + (s % 3) * STAGE_B;
        ldA(tb, 1, A1h, A1l);
        mmaHalf(tb, 0, A0h, A0l);

        CP_WAIT(0);
        __syncthreads();
        if (s + 2 < S) cp_stage((s + 2) % 3, s + 2);
        CP_COMMIT();
        if (s + 1 < S) {
            const uint32_t tbn = sb + ((s + 1) % 3) * STAGE_B;
            ldA(tbn, 0, A0h, A0l);
        }
        mmaHalf(tb, 1, A1h, A1l);
    }

    // ---- epilogue ----
    if (EPI == 0) {
        float rsum8[8];
        float csum16[16];
        #pragma unroll
        for (int j = 0; j < 8; j++) rsum8[j] = 0.f;
        #pragma unroll
        for (int q = 0; q < 16; q++) csum16[q] = 0.f;
        bf16* cH = CoH + (size_t)z * cB; bf16* cL = CoL + (size_t)z * cB;
        #pragma unroll
        for (int mb = 0; mb < 4; mb++) {
            int r0 = m0 + wm * 64 + mb * 16 + gid;
            int r1 = r0 + 8;
            #pragma unroll
            for (int nb = 0; nb < 8; nb++) {
                int col = n0 + wn * 64 + nb * 8 + tig * 2;
                float p0 = __expf(acc[mb][nb][0] - SHIFTC);
                float p1 = __expf(acc[mb][nb][1] - SHIFTC);
                float p2 = __expf(acc[mb][nb][2] - SHIFTC);
                float p3 = __expf(acc[mb][nb][3] - SHIFTC);
                size_t o0 = (size_t)r0 * ldc + col, o1 = (size_t)r1 * ldc + col;
                bf16 h, l; __nv_bfloat162 hv, lv;
                bsplit(p0, h, l); hv.x = h; lv.x = l;
                bsplit(p1, h, l); hv.y = h; lv.y = l;
                *(__nv_bfloat162*)(cH + o0) = hv; *(__nv_bfloat162*)(cL + o0) = lv;
                bsplit(p2, h, l); hv.x = h; lv.x = l;
                bsplit(p3, h, l); hv.y = h; lv.y = l;
                *(__nv_bfloat162*)(cH + o1) = hv; *(__nv_bfloat162*)(cL + o1) = lv;
                rsum8[mb*2]   += p0 + p1;
                rsum8[mb*2+1] += p2 + p3;
                csum16[nb*2]   += p0 + p2;
                csum16[nb*2+1] += p1 + p3;
            }
        }
        #pragma unroll
        for (int o = 1; o <= 2; o <<= 1)
            #pragma unroll
            for (int j = 0; j < 8; j++)
                rsum8[j] += __shfl_xor_sync(0xffffffffu, rsum8[j], o);
        if (tig == 0) {
            #pragma unroll
            for (int j = 0; j < 8; j++) {
                int row = m0 + wm * 64 + (j >> 1) * 16 + (j & 1) * 8 + gid;
                size_t o = ((size_t)z * 8 + by * 2 + wn) * (size_t)LCn + row;
                PrS[o] = rsum8[j];
            }
        }
        #pragma unroll
        for (int o = 4; o <= 16; o <<= 1)
            #pragma unroll
            for (int q = 0; q < 16; q++)
                csum16[q] += __shfl_xor_sync(0xffffffffu, csum16[q], o);
        if (gid == 0) {
            #pragma unroll
            for (int q = 0; q < 16; q++) {
                int col = n0 + wn * 64 + (q >> 1) * 8 + tig * 2 + (q & 1);
                size_t o = ((size_t)z * 32 + bx * 2 + wm) * (size_t)LRn + col;
                PcS[o] = csum16[q];
            }
        }
        return;
    }

    #pragma unroll
    for (int mb = 0; mb < 4; mb++) {
        int r0 = m0 + wm * 64 + mb * 16 + gid;
        int r1 = r0 + 8;
        float s0 = 1.f, s1 = 1.f;
        if (EPI == 1) {
            s0 = 1.0f / rsum[(size_t)z * sB + r0];
            s1 = 1.0f / rsum[(size_t)z * sB + r1];
        }
        #pragma unroll
        for (int nb = 0; nb < 8; nb++) {
            int col = n0 + wn * 64 + nb * 8 + tig * 2;
            float c0 = acc[mb][nb][0], c1 = acc[mb][nb][1];
            float c2 = acc[mb][nb][2], c3 = acc[mb][nb][3];
            if (EPI == 2) {
                float b0v = bias[col], b1v = bias[col + 1];
                float* C = Cf;
                *(float2*)(C + (size_t)r0 * ldc + col) =
                    make_float2(fmaxf(c0 + b0v, 0.f), fmaxf(c1 + b1v, 0.f));
                *(float2*)(C + (size_t)r1 * ldc + col) =
                    make_float2(fmaxf(c2 + b0v, 0.f), fmaxf(c3 + b1v, 0.f));
            } else {
                c0 *= s0; c1 *= s0; c2 *= s1; c3 *= s1;
                const float* X = Xf + (size_t)z * cB;
                bf16* cH = CoH + (size_t)z * cB; bf16* cL = CoL + (size_t)z * cB;
                bf16* pH = PoH + (size_t)z * cB; bf16* pL = PoL + (size_t)z * cB;
                size_t o0 = (size_t)r0 * ldc + col, o1 = (size_t)r1 * ldc + col;
                float2 x0 = *(const float2*)(X + o0);
                float2 x1 = *(const float2*)(X + o1);
                bf16 h, l; __nv_bfloat162 hv, lv;
                bsplit(c0, h, l); hv.x = h; lv.x = l;
                bsplit(c1, h, l); hv.y = h; lv.y = l;
                *(__nv_bfloat162*)(cH + o0) = hv; *(__nv_bfloat162*)(cL + o0) = lv;
                bsplit(c2, h, l); hv.x = h; lv.x = l;
                bsplit(c3, h, l); hv.y = h; lv.y = l;
                *(__nv_bfloat162*)(cH + o1) = hv; *(__nv_bfloat162*)(cL + o1) = lv;
                bsplit(x0.x * c0, h, l); hv.x = h; lv.x = l;
                bsplit(x0.y * c1, h, l); hv.y = h; lv.y = l;
                *(__nv_bfloat162*)(pH + o0) = hv; *(__nv_bfloat162*)(pL + o0) = lv;
                bsplit(x1.x * c2, h, l); hv.x = h; lv.x = l;
                bsplit(x1.y * c3, h, l); hv.y = h; lv.y = l;
                *(__nv_bfloat162*)(pH + o1) = hv; *(__nv_bfloat162*)(pL + o1) = lv;
            }
        }
    }
}

// ============================================================================
// Kernels
// ============================================================================
__global__ void __launch_bounds__(128, 2) k_gemm0() {
    gemm_core<0, 0>(g_csH, g_csL, g_csH, g_csL, g_csH, g_csL, g_rsH, g_rsL,
                    nullptr, nullptr, nullptr, nullptr, g_EH, g_EL, nullptr, nullptr,
                    g_prS, g_pcS,
                    Dn, Dn, Dn, LRn,
                    (size_t)LCn * Dn, (size_t)LRn * Dn, (size_t)LCn * LRn, 0,
                    blockIdx.x, blockIdx.y, blockIdx.z);
}

__global__ void __launch_bounds__(128, 2) k_cd(const float* __restrict__ cs) {
    gemm_core<1, 0>(g_EH, g_EL, g_EH, g_EL, g_EH, g_EL, g_rsTH, g_rsTL,
                    g_asum, cs, nullptr, nullptr, g_cdH, g_cdL, g_pcH, g_pcL,
                    nullptr, nullptr,
                    LRn, LRn, LRn, Dn,
                    (size_t)LCn * LRn, (size_t)Dn * LRn, (size_t)LCn * Dn, LCn,
                    blockIdx.x, blockIdx.y, blockIdx.z);
}

__global__ void __launch_bounds__(128, 2) k_rd(const float* __restrict__ rs) {
    gemm_core<1, 1>(g_EH, g_EL, g_EH, g_EL, g_EH, g_EL, g_csTH, g_csTL,
                    g_bsum, rs, nullptr, nullptr, g_rdH, g_rdL, g_prH, g_prL,
                    nullptr, nullptr,
                    LCn, LRn, LCn, Dn,
                    (size_t)LCn * LRn, (size_t)Dn * LCn, (size_t)LRn * Dn, LRn,
                    blockIdx.x, blockIdx.y, blockIdx.z);
}

// FC1 (x<512) + FC2 fused — same K, balanced CTA durations.
__global__ void __launch_bounds__(128, 2) k_fc(const float* __restrict__ b1,
                                               const float* __restrict__ b2,
                                               float* __restrict__ cl,
                                               float* __restrict__ rl) {
    if (blockIdx.x < 512) {
        gemm_core<2, 0>(g_csH, g_csL, g_cdH, g_cdL, g_pcH, g_pcL, g_W1H, g_W1L,
                        nullptr, nullptr, b1, cl, nullptr, nullptr, nullptr, nullptr,
                        nullptr, nullptr,
                        3 * Dn, Dn, 3 * Dn, Hn, 0, 0, 0, 0,
                        blockIdx.x, 0, 0);
    } else {
        gemm_core<2, 0>(g_rsH, g_rsL, g_rdH, g_rdL, g_prH, g_prL, g_W2H, g_W2L,
                        nullptr, nullptr, b2, rl, nullptr, nullptr, nullptr, nullptr,
                        nullptr, nullptr,
                        3 * Dn, Dn, 3 * Dn, Hn, 0, 0, 0, 0,
                        blockIdx.x - 512, 0, 0);
    }
}

// ============================================================================
// Sum merges (plain adds — shift-invariant softmax needs no max)
// ============================================================================
__global__ void k_merge_both() {
    int idx = blockIdx.x * 256 + threadIdx.x;
    if (idx < MC) {
        int b = idx >> 11, c = idx & (LCn - 1);
        float s = 0.f;
        #pragma unroll
        for (int j = 0; j < 8; j++)
            s += g_prS[((size_t)b * 8 + j) * LCn + c];
        g_asum[idx] = s;
    } else {
        int i2 = idx - MC;
        int b = i2 >> 9, r = i2 & (LRn - 1);
        float s = 0.f;
        #pragma unroll
        for (int j = 0; j < 32; j++)
            s += g_pcS[((size_t)b * 32 + j) * LRn + r];
        g_bsum[i2] = s;
    }
}

// ============================================================================
// Fused preprocessing: rs (y<16) + cs (y>=16) in one launch.
// ============================================================================
__global__ void k_splitboth(const float* __restrict__ rs, const float* __restrict__ cs,
                            bf16* __restrict__ rsH, bf16* __restrict__ rsL,
                            bf16* __restrict__ rtH, bf16* __restrict__ rtL,
                            bf16* __restrict__ csH, bf16* __restrict__ csL,
                            bf16* __restrict__ ctH, bf16* __restrict__ ctL) {
    __shared__ float t[32][33];
    int b = blockIdx.z;
    const float* src; bf16 *H, *L, *HT, *LT; int rows, r0;
    if (blockIdx.y < 16) {
        src = rs; H = rsH; L = rsL; HT = rtH; LT = rtL;
        rows = LRn; r0 = blockIdx.y * 32;
    } else {
        src = cs; H = csH; L = csL; HT = ctH; LT = ctL;
        rows = LCn; r0 = (blockIdx.y - 16) * 32;
    }
    const float* s = src + (size_t)b * rows * Dn;
    size_t base = (size_t)b * rows * Dn;
    int c0 = blockIdx.x * 32;
    int x = threadIdx.x, y = threadIdx.y;
    #pragma unroll
    for (int i = 0; i < 32; i += 8) {
        int row = r0 + y + i;
        float v = s[(size_t)row * Dn + c0 + x];
        t[y + i][x] = v;
        bf16 h, l; bsplit(v, h, l);
        size_t o = base + (size_t)row * Dn + c0 + x;
        H[o] = h; L[o] = l;
    }
    __syncthreads();
    #pragma unroll
    for (int i = 0; i < 32; i += 8) {
        float v = t[x][y + i];
        bf16 h, l; bsplit(v, h, l);
        size_t o = base + (size_t)(c0 + y + i) * rows + r0 + x;
        HT[o] = h; LT[o] = l;
    }
}

__global__ void k_wcomb_split(const float* __restrict__ W1, const float* __restrict__ W2) {
    int i = blockIdx.x * 256 + threadIdx.x;
    if (i >= Hn * Dn) return;
    int hh = i >> 8, d = i & (Dn - 1);
    const float* w1 = W1 + (size_t)hh * 4 * Dn;
    const float* w2 = W2 + (size_t)hh * 4 * Dn;
    float v; bf16 h, l;
    size_t base = (size_t)hh * 3 * Dn + d;
    v = w1[d] + w1[2 * Dn + d];      bsplit(v, h, l); g_W1H[base] = h;          g_W1L[base] = l;
    v = w1[Dn + d] - w1[2 * Dn + d]; bsplit(v, h, l); g_W1H[base + Dn] = h;     g_W1L[base + Dn] = l;
    v = w1[3 * Dn + d];              bsplit(v, h, l); g_W1H[base + 2 * Dn] = h; g_W1L[base + 2 * Dn] = l;
    v = w2[d] + w2[2 * Dn + d];      bsplit(v, h, l); g_W2H[base] = h;          g_W2L[base] = l;
    v = w2[Dn + d] - w2[2 * Dn + d]; bsplit(v, h, l); g_W2H[base + Dn] = h;     g_W2L[base + Dn] = l;
    v = w2[3 * Dn + d];              bsplit(v, h, l); g_W2H[base + 2 * Dn] = h; g_W2L[base + 2 * Dn] = l;
}

// ============================================================================
extern "C" void kernel_launch(void* const* d_in, const int* in_sizes, int n_in,
                              void* d_out, int out_size) {
    const float* cs = (const float*)d_in[0];
    const float* rs = (const float*)d_in[1];
    const float* W1 = (const float*)d_in[2];
    const float* b1 = (const float*)d_in[3];
    const float* W2 = (const float*)d_in[4];
    const float* b2 = (const float*)d_in[5];
    float* cl = (float*)d_out;
    float* rl = cl + (size_t)MC * Hn;

    bf16 *rsH, *rsL, *rtH, *rtL, *csH, *csL, *ctH, *ctL;
    cudaGetSymbolAddress((void**)&rsH, g_rsH); cudaGetSymbolAddress((void**)&rsL, g_rsL);
    cudaGetSymbolAddress((void**)&rtH, g_rsTH); cudaGetSymbolAddress((void**)&rtL, g_rsTL);
    cudaGetSymbolAddress((void**)&csH, g_csH); cudaGetSymbolAddress((void**)&csL, g_csL);
    cudaGetSymbolAddress((void**)&ctH, g_csTH); cudaGetSymbolAddress((void**)&ctL, g_csTL);

    cudaFuncSetAttribute(k_gemm0, cudaFuncAttributeMaxDynamicSharedMemorySize, SMEM_DYN);
    cudaFuncSetAttribute(k_cd,    cudaFuncAttributeMaxDynamicSharedMemorySize, SMEM_DYN);
    cudaFuncSetAttribute(k_rd,    cudaFuncAttributeMaxDynamicSharedMemorySize, SMEM_DYN);
    cudaFuncSetAttribute(k_fc,    cudaFuncAttributeMaxDynamicSharedMemorySize, SMEM_DYN);

    k_wcomb_split<<<(Hn * Dn + 255) / 256, 256>>>(W1, W2);
    k_splitboth<<<dim3(8, 80, Bn), dim3(32, 8)>>>(rs, cs, rsH, rsL, rtH, rtL,
                                                  csH, csL, ctH, ctL);

    // GEMM0: exp(cs*rs^T - 64) split pairs + partial sums
    k_gemm0<<<dim3(16, 4, Bn), 128, SMEM_DYN>>>();

    k_merge_both<<<(MC + MR) / 256, 256>>>();

    // cd: A = Ê row-major (K=512), B = rsT pair; scale 1/asum
    k_cd<<<dim3(16, 2, Bn), 128, SMEM_DYN>>>(cs);

    // rd: A = Ê^T via trans-ldmatrix (K=2048), B = csT pair; scale 1/bsum
    k_rd<<<dim3(4, 2, Bn), 128, SMEM_DYN>>>(rs);

    // FC1 + FC2 fused (balanced K=768 CTAs)
    k_fc<<<dim3(640, 1, 1), 128, SMEM_DYN>>>(b1, b2, cl, rl);
}

// round 15
// speedup vs baseline: 1.0553x; 1.0553x over previous
#include <cuda_runtime.h>
#include <cuda_bf16.h>
#include <math.h>
#include <stdint.h>

#define Bn  32
#define LCn 2048
#define LRn 512
#define Dn  256
#define Hn  128
#define MC  (Bn * LCn)
#define MR  (Bn * LRn)
#define SHIFTC 64.0f

typedef __nv_bfloat16 bf16;

// -------- scratch --------
static __device__ bf16 g_EH [(size_t)Bn * LCn * LRn], g_EL [(size_t)Bn * LCn * LRn];
static __device__ bf16 g_csH[(size_t)Bn * LCn * Dn],  g_csL[(size_t)Bn * LCn * Dn];
static __device__ bf16 g_rsH[(size_t)Bn * LRn * Dn],  g_rsL[(size_t)Bn * LRn * Dn];
static __device__ bf16 g_cdH[(size_t)Bn * LCn * Dn],  g_cdL[(size_t)Bn * LCn * Dn];
static __device__ bf16 g_pcH[(size_t)Bn * LCn * Dn],  g_pcL[(size_t)Bn * LCn * Dn];
static __device__ bf16 g_rdH[(size_t)Bn * LRn * Dn],  g_rdL[(size_t)Bn * LRn * Dn];
static __device__ bf16 g_prH[(size_t)Bn * LRn * Dn],  g_prL[(size_t)Bn * LRn * Dn];
static __device__ bf16 g_W1H[Hn * 3 * Dn], g_W1L[Hn * 3 * Dn];
static __device__ bf16 g_W2H[Hn * 3 * Dn], g_W2L[Hn * 3 * Dn];
static __device__ float g_asum[MC];
static __device__ float g_bsum[MR];
static __device__ float g_prS[(size_t)Bn * 8 * LCn];     // row-sum partials
static __device__ float g_pcS[(size_t)Bn * 32 * LRn];    // col-sum partials

// ======================== helpers =============================
__device__ __forceinline__ uint32_t smem_u32(const void* p) {
    uint32_t a;
    asm("{ .reg .u64 t; cvta.to.shared.u64 t, %1; cvt.u32.u64 %0, t; }" : "=r"(a) : "l"(p));
    return a;
}

#define LDSM4(r, addr) \
    asm volatile("ldmatrix.sync.aligned.m8n8.x4.shared.b16 {%0,%1,%2,%3}, [%4];" \
        : "=r"((r)[0]), "=r"((r)[1]), "=r"((r)[2]), "=r"((r)[3]) : "r"(addr))

#define LDSM4T(r, addr) \
    asm volatile("ldmatrix.sync.aligned.m8n8.x4.trans.shared.b16 {%0,%1,%2,%3}, [%4];" \
        : "=r"((r)[0]), "=r"((r)[1]), "=r"((r)[2]), "=r"((r)[3]) : "r"(addr))

#define MMA_BF16(c, a, b0, b1) \
    asm volatile("mma.sync.aligned.m16n8k16.row.col.f32.bf16.bf16.f32 " \
        "{%0,%1,%2,%3}, {%4,%5,%6,%7}, {%8,%9}, {%0,%1,%2,%3};" \
        : "+f"((c)[0]), "+f"((c)[1]), "+f"((c)[2]), "+f"((c)[3]) \
        : "r"((a)[0]), "r"((a)[1]), "r"((a)[2]), "r"((a)[3]), "r"(b0), "r"(b1))

#define CP16(dst, src) \
    asm volatile("cp.async.cg.shared.global [%0], [%1], 16;" :: "r"(dst), "l"(src))
#define CP_COMMIT() asm volatile("cp.async.commit_group;" ::: "memory")
#define CP_WAIT(n)  asm volatile("cp.async.wait_group %0;" :: "n"(n) : "memory")

__device__ __forceinline__ void bsplit(float v, bf16& h, bf16& l) {
    h = __float2bfloat16(v);
    l = __float2bfloat16(v - __bfloat162float(h));
}

// non-trans smem tile: [rows][32 k] bf16, 64B rows; conflict-free swizzle.
__device__ __forceinline__ uint32_t toff16(int row, int u) {
    return (row << 6) + ((u ^ ((row >> 1) & 3)) << 4);
}

#define SM_AH 0
#define SM_AL 8192
#define SM_BH 16384
#define SM_BL 24576
#define STAGE_B 32768
#define SMEM_DYN (3 * STAGE_B)

// ============================================================================
// NT GEMM on pre-split bf16 pairs: C[128,128] = A[128,K]*B[128,K]^T
// (3 products HH+HL+LH).
// TRA=1: A streamed from row-major [K][M] source via ldmatrix.trans.
// TRB=1: B streamed from row-major [K][N] source via ldmatrix.trans.
// EPI 0: emit exp(acc-SHIFT) split pairs + plain row/col partial sums.
// EPI 1: scale 1/rsum, emit split pairs + split(X*scaled).  EPI 2: relu+bias.
// ============================================================================
template<int EPI, int TRA, int TRB>
__global__ void __launch_bounds__(128, 2) k_gemm(
    const bf16* __restrict__ AH0, const bf16* __restrict__ AL0,
    const bf16* __restrict__ AH1, const bf16* __restrict__ AL1,
    const bf16* __restrict__ AH2, const bf16* __restrict__ AL2,
    const bf16* __restrict__ BH,  const bf16* __restrict__ BL,
    const float* __restrict__ rsum, const float* __restrict__ Xf,
    const float* __restrict__ bias, float* __restrict__ Cf,
    bf16* __restrict__ CoH, bf16* __restrict__ CoL,
    bf16* __restrict__ PoH, bf16* __restrict__ PoL,
    float* __restrict__ PrS, float* __restrict__ PcS,
    int K, int lda, int ldb, int ldc,
    size_t aB, size_t bB, size_t cB, int sB)
{
    extern __shared__ __align__(16) uint8_t sm[];
    const uint32_t sb = smem_u32(sm);
    const int tid = threadIdx.x;
    const int z = blockIdx.z;
    const int m0 = blockIdx.x * 128, n0 = blockIdx.y * 128;
    const bf16* aH0 = AH0 + (size_t)z * aB;
    const bf16* aL0 = AL0 + (size_t)z * aB;
    const bf16* bH  = BH  + (size_t)z * bB;
    const bf16* bL  = BL  + (size_t)z * bB;

    const int lane = tid & 31, wid = tid >> 5;
    const int wm = wid & 1, wn = wid >> 1;
    const int gid = lane >> 2, tig = lane & 3;

    float acc[4][8][4];
    #pragma unroll
    for (int a = 0; a < 4; a++)
        #pragma unroll
        for (int b = 0; b < 8; b++)
            #pragma unroll
            for (int c = 0; c < 4; c++) acc[a][b][c] = 0.f;

    const int S = K >> 5;

    auto cp_stage = [&](int buf, int kc) {
        const uint32_t tb = sb + buf * STAGE_B;
        const int k0 = kc << 5;
        if (TRA) {
            // A tile [k=32 rows][m=128], 256B rows, unit swizzle u ^= (row&7)
            #pragma unroll
            for (int i = 0; i < 4; i++) {
                int idx = tid + i * 128;
                int row = idx >> 4, u = idx & 15;
                uint32_t up = (uint32_t)(u ^ (row & 7));
                uint32_t off = row * 256 + up * 16;
                const size_t g = (size_t)(k0 + row) * lda + m0 + u * 8;
                CP16(tb + SM_AH + off, aH0 + g);
                CP16(tb + SM_AL + off, aL0 + g);
            }
        } else {
            const bf16* aH = aH0; const bf16* aL = aL0;
            int kk = k0;
            if (EPI == 2) {
                int seg = k0 >> 8; kk = k0 & 255;
                if (seg == 1) { aH = AH1; aL = AL1; }
                else if (seg == 2) { aH = AH2; aL = AL2; }
            }
            #pragma unroll
            for (int i = 0; i < 4; i++) {
                int idx = tid + i * 128;
                int row = idx >> 2, u = idx & 3;
                uint32_t off = toff16(row, u);
                const size_t g = (size_t)(m0 + row) * lda + kk + u * 8;
                CP16(tb + SM_AH + off, aH + g);
                CP16(tb + SM_AL + off, aL + g);
            }
        }
        if (TRB) {
            // B tile [k=32 rows][n=128], 256B rows, unit swizzle u ^= (row&7)
            #pragma unroll
            for (int i = 0; i < 4; i++) {
                int idx = tid + i * 128;
                int row = idx >> 4, u = idx & 15;
                uint32_t up = (uint32_t)(u ^ (row & 7));
                uint32_t off = row * 256 + up * 16;
                const size_t g = (size_t)(k0 + row) * ldb + n0 + u * 8;
                CP16(tb + SM_BH + off, bH + g);
                CP16(tb + SM_BL + off, bL + g);
            }
        } else {
            #pragma unroll
            for (int i = 0; i < 4; i++) {
                int idx = tid + i * 128;
                int row = idx >> 2, u = idx & 3;
                uint32_t off = toff16(row, u);
                const size_t g = (size_t)(n0 + row) * ldb + k0 + u * 8;
                CP16(tb + SM_BH + off, bH + g);
                CP16(tb + SM_BL + off, bL + g);
            }
        }
    };

    auto ldA = [&](uint32_t tb, int kb, uint32_t (&ah)[4][4], uint32_t (&al)[4][4]) {
        if (TRA) {
            int rowk = kb * 16 + ((lane >> 4) << 3) + (lane & 7);
            #pragma unroll
            for (int mb = 0; mb < 4; mb++) {
                int um = wm * 8 + mb * 2 + ((lane >> 3) & 1);
                uint32_t up = (uint32_t)(um ^ (rowk & 7));
                uint32_t addr = tb + rowk * 256 + up * 16;
                LDSM4T(ah[mb], addr + SM_AH);
                LDSM4T(al[mb], addr + SM_AL);
            }
        } else {
            #pragma unroll
            for (int mb = 0; mb < 4; mb++) {
                int row = wm * 64 + mb * 16 + (lane & 15);
                uint32_t off = toff16(row, kb * 2 + (lane >> 4));
                LDSM4(ah[mb], tb + SM_AH + off);
                LDSM4(al[mb], tb + SM_AL + off);
            }
        }
    };

    auto mmaHalf = [&](uint32_t tb, int kb, uint32_t (&ah)[4][4], uint32_t (&al)[4][4]) {
        #pragma unroll
        for (int np = 0; np < 4; np++) {
            uint32_t bh[4], bl[4];
            if (TRB) {
                // matrices ordered n-half-major: lanes0-7 k0-7/n-unit even,
                // 8-15 k8-15/even, 16-23 k0-7/odd, 24-31 k8-15/odd
                int rowk = kb * 16 + ((lane >> 3) & 1) * 8 + (lane & 7);
                int un = wn * 8 + np * 2 + (lane >> 4);
                uint32_t up = (uint32_t)(un ^ (rowk & 7));
                uint32_t addr = tb + rowk * 256 + up * 16;
                LDSM4T(bh, addr + SM_BH);
                LDSM4T(bl, addr + SM_BL);
            } else {
                int nrow = wn * 64 + np * 16 + (lane & 7) + ((lane >> 4) << 3);
                uint32_t off = toff16(nrow, kb * 2 + ((lane >> 3) & 1));
                LDSM4(bh, tb + SM_BH + off);
                LDSM4(bl, tb + SM_BL + off);
            }
            #pragma unroll
            for (int nb = 0; nb < 2; nb++)
                #pragma unroll
                for (int mb = 0; mb < 4; mb++)
                    MMA_BF16(acc[mb][np*2+nb], ah[mb], bh[nb*2], bh[nb*2+1]);
            #pragma unroll
            for (int nb = 0; nb < 2; nb++)
                #pragma unroll
                for (int mb = 0; mb < 4; mb++)
                    MMA_BF16(acc[mb][np*2+nb], ah[mb], bl[nb*2], bl[nb*2+1]);
            #pragma unroll
            for (int nb = 0; nb < 2; nb++)
                #pragma unroll
                for (int mb = 0; mb < 4; mb++)
                    MMA_BF16(acc[mb][np*2+nb], al[mb], bh[nb*2], bh[nb*2+1]);
        }
    };

    uint32_t A0h[4][4], A0l[4][4], A1h[4][4], A1l[4][4];

    cp_stage(0, 0); CP_COMMIT();
    if (S > 1) cp_stage(1, 1);
    CP_COMMIT();
    CP_WAIT(1);
    __syncthreads();
    ldA(sb, 0, A0h, A0l);

    for (int s = 0; s < S; s++) {
        const uint32_t tb = sb + (s % 3) * STAGE_B;
        ldA(tb, 1, A1h, A1l);
        mmaHalf(tb, 0, A0h, A0l);

        CP_WAIT(0);
        __syncthreads();
        if (s + 2 < S) cp_stage((s + 2) % 3, s + 2);
        CP_COMMIT();
        if (s + 1 < S) {
            const uint32_t tbn = sb + ((s + 1) % 3) * STAGE_B;
            ldA(tbn, 0, A0h, A0l);
        }
        mmaHalf(tb, 1, A1h, A1l);
    }

    // ---- epilogue ----
    if (EPI == 0) {
        float rsum8[8];
        float csum16[16];
        #pragma unroll
        for (int j = 0; j < 8; j++) rsum8[j] = 0.f;
        #pragma unroll
        for (int q = 0; q < 16; q++) csum16[q] = 0.f;
        bf16* cH = CoH + (size_t)z * cB; bf16* cL = CoL + (size_t)z * cB;
        #pragma unroll
        for (int mb = 0; mb < 4; mb++) {
            int r0 = m0 + wm * 64 + mb * 16 + gid;
            int r1 = r0 + 8;
            #pragma unroll
            for (int nb = 0; nb < 8; nb++) {
                int col = n0 + wn * 64 + nb * 8 + tig * 2;
                float p0 = __expf(acc[mb][nb][0] - SHIFTC);
                float p1 = __expf(acc[mb][nb][1] - SHIFTC);
                float p2 = __expf(acc[mb][nb][2] - SHIFTC);
                float p3 = __expf(acc[mb][nb][3] - SHIFTC);
                size_t o0 = (size_t)r0 * ldc + col, o1 = (size_t)r1 * ldc + col;
                bf16 h, l; __nv_bfloat162 hv, lv;
                bsplit(p0, h, l); hv.x = h; lv.x = l;
                bsplit(p1, h, l); hv.y = h; lv.y = l;
                *(__nv_bfloat162*)(cH + o0) = hv; *(__nv_bfloat162*)(cL + o0) = lv;
                bsplit(p2, h, l); hv.x = h; lv.x = l;
                bsplit(p3, h, l); hv.y = h; lv.y = l;
                *(__nv_bfloat162*)(cH + o1) = hv; *(__nv_bfloat162*)(cL + o1) = lv;
                rsum8[mb*2]   += p0 + p1;
                rsum8[mb*2+1] += p2 + p3;
                csum16[nb*2]   += p0 + p2;
                csum16[nb*2+1] += p1 + p3;
            }
        }
        #pragma unroll
        for (int o = 1; o <= 2; o <<= 1)
            #pragma unroll
            for (int j = 0; j < 8; j++)
                rsum8[j] += __shfl_xor_sync(0xffffffffu, rsum8[j], o);
        if (tig == 0) {
            #pragma unroll
            for (int j = 0; j < 8; j++) {
                int row = m0 + wm * 64 + (j >> 1) * 16 + (j & 1) * 8 + gid;
                size_t o = ((size_t)z * 8 + blockIdx.y * 2 + wn) * (size_t)LCn + row;
                PrS[o] = rsum8[j];
            }
        }
        #pragma unroll
        for (int o = 4; o <= 16; o <<= 1)
            #pragma unroll
            for (int q = 0; q < 16; q++)
                csum16[q] += __shfl_xor_sync(0xffffffffu, csum16[q], o);
        if (gid == 0) {
            #pragma unroll
            for (int q = 0; q < 16; q++) {
                int col = n0 + wn * 64 + (q >> 1) * 8 + tig * 2 + (q & 1);
                size_t o = ((size_t)z * 32 + blockIdx.x * 2 + wm) * (size_t)LRn + col;
                PcS[o] = csum16[q];
            }
        }
        return;
    }

    #pragma unroll
    for (int mb = 0; mb < 4; mb++) {
        int r0 = m0 + wm * 64 + mb * 16 + gid;
        int r1 = r0 + 8;
        float s0 = 1.f, s1 = 1.f;
        if (EPI == 1) {
            s0 = 1.0f / rsum[(size_t)z * sB + r0];
            s1 = 1.0f / rsum[(size_t)z * sB + r1];
        }
        #pragma unroll
        for (int nb = 0; nb < 8; nb++) {
            int col = n0 + wn * 64 + nb * 8 + tig * 2;
            float c0 = acc[mb][nb][0], c1 = acc[mb][nb][1];
            float c2 = acc[mb][nb][2], c3 = acc[mb][nb][3];
            if (EPI == 2) {
                float b0v = bias[col], b1v = bias[col + 1];
                float* C = Cf;
                *(float2*)(C + (size_t)r0 * ldc + col) =
                    make_float2(fmaxf(c0 + b0v, 0.f), fmaxf(c1 + b1v, 0.f));
                *(float2*)(C + (size_t)r1 * ldc + col) =
                    make_float2(fmaxf(c2 + b0v, 0.f), fmaxf(c3 + b1v, 0.f));
            } else {
                c0 *= s0; c1 *= s0; c2 *= s1; c3 *= s1;
                const float* X = Xf + (size_t)z * cB;
                bf16* cH = CoH + (size_t)z * cB; bf16* cL = CoL + (size_t)z * cB;
                bf16* pH = PoH + (size_t)z * cB; bf16* pL = PoL + (size_t)z * cB;
                size_t o0 = (size_t)r0 * ldc + col, o1 = (size_t)r1 * ldc + col;
                float2 x0 = *(const float2*)(X + o0);
                float2 x1 = *(const float2*)(X + o1);
                bf16 h, l; __nv_bfloat162 hv, lv;
                bsplit(c0, h, l); hv.x = h; lv.x = l;
                bsplit(c1, h, l); hv.y = h; lv.y = l;
                *(__nv_bfloat162*)(cH + o0) = hv; *(__nv_bfloat162*)(cL + o0) = lv;
                bsplit(c2, h, l); hv.x = h; lv.x = l;
                bsplit(c3, h, l); hv.y = h; lv.y = l;
                *(__nv_bfloat162*)(cH + o1) = hv; *(__nv_bfloat162*)(cL + o1) = lv;
                bsplit(x0.x * c0, h, l); hv.x = h; lv.x = l;
                bsplit(x0.y * c1, h, l); hv.y = h; lv.y = l;
                *(__nv_bfloat162*)(pH + o0) = hv; *(__nv_bfloat162*)(pL + o0) = lv;
                bsplit(x1.x * c2, h, l); hv.x = h; lv.x = l;
                bsplit(x1.y * c3, h, l); hv.y = h; lv.y = l;
                *(__nv_bfloat162*)(pH + o1) = hv; *(__nv_bfloat162*)(pL + o1) = lv;
            }
        }
    }
}

// ============================================================================
// Sum merges (plain adds — shift-invariant softmax needs no max)
// ============================================================================
__global__ void k_merge_both() {
    int idx = blockIdx.x * 256 + threadIdx.x;
    if (idx < MC) {
        int b = idx >> 11, c = idx & (LCn - 1);
        float s = 0.f;
        #pragma unroll
        for (int j = 0; j < 8; j++)
            s += g_prS[((size_t)b * 8 + j) * LCn + c];
        g_asum[idx] = s;
    } else {
        int i2 = idx - MC;
        int b = i2 >> 9, r = i2 & (LRn - 1);
        float s = 0.f;
        #pragma unroll
        for (int j = 0; j < 32; j++)
            s += g_pcS[((size_t)b * 32 + j) * LRn + r];
        g_bsum[i2] = s;
    }
}

// ============================================================================
// Elementwise split (no transpose needed anymore)
// ============================================================================
__global__ void k_split(const float* __restrict__ src, bf16* __restrict__ H,
                        bf16* __restrict__ L) {
    size_t e4 = ((size_t)blockIdx.x * 256 + threadIdx.x) * 4;
    float4 v = *(const float4*)(src + e4);
    bf16 h, l; __nv_bfloat162 h01, h23, l01, l23;
    bsplit(v.x, h, l); h01.x = h; l01.x = l;
    bsplit(v.y, h, l); h01.y = h; l01.y = l;
    bsplit(v.z, h, l); h23.x = h; l23.x = l;
    bsplit(v.w, h, l); h23.y = h; l23.y = l;
    *(__nv_bfloat162*)(H + e4) = h01; *(__nv_bfloat162*)(H + e4 + 2) = h23;
    *(__nv_bfloat162*)(L + e4) = l01; *(__nv_bfloat162*)(L + e4 + 2) = l23;
}

__global__ void k_wcomb_split(const float* __restrict__ W1, const float* __restrict__ W2) {
    int i = blockIdx.x * 256 + threadIdx.x;
    if (i >= Hn * Dn) return;
    int hh = i >> 8, d = i & (Dn - 1);
    const float* w1 = W1 + (size_t)hh * 4 * Dn;
    const float* w2 = W2 + (size_t)hh * 4 * Dn;
    float v; bf16 h, l;
    size_t base = (size_t)hh * 3 * Dn + d;
    v = w1[d] + w1[2 * Dn + d];      bsplit(v, h, l); g_W1H[base] = h;          g_W1L[base] = l;
    v = w1[Dn + d] - w1[2 * Dn + d]; bsplit(v, h, l); g_W1H[base + Dn] = h;     g_W1L[base + Dn] = l;
    v = w1[3 * Dn + d];              bsplit(v, h, l); g_W1H[base + 2 * Dn] = h; g_W1L[base + 2 * Dn] = l;
    v = w2[d] + w2[2 * Dn + d];      bsplit(v, h, l); g_W2H[base] = h;          g_W2L[base] = l;
    v = w2[Dn + d] - w2[2 * Dn + d]; bsplit(v, h, l); g_W2H[base + Dn] = h;     g_W2L[base + Dn] = l;
    v = w2[3 * Dn + d];              bsplit(v, h, l); g_W2H[base + 2 * Dn] = h; g_W2L[base + 2 * Dn] = l;
}

// ============================================================================
extern "C" void kernel_launch(void* const* d_in, const int* in_sizes, int n_in,
                              void* d_out, int out_size) {
    const float* cs = (const float*)d_in[0];
    const float* rs = (const float*)d_in[1];
    const float* W1 = (const float*)d_in[2];
    const float* b1 = (const float*)d_in[3];
    const float* W2 = (const float*)d_in[4];
    const float* b2 = (const float*)d_in[5];
    float* cl = (float*)d_out;
    float* rl = cl + (size_t)MC * Hn;

    bf16 *eH, *eL, *csH, *csL, *rsH, *rsL;
    bf16 *cdH, *cdL, *pcH, *pcL, *rdH, *rdL, *prH, *prL, *w1H, *w1L, *w2H, *w2L;
    cudaGetSymbolAddress((void**)&eH, g_EH);   cudaGetSymbolAddress((void**)&eL, g_EL);
    cudaGetSymbolAddress((void**)&csH, g_csH); cudaGetSymbolAddress((void**)&csL, g_csL);
    cudaGetSymbolAddress((void**)&rsH, g_rsH); cudaGetSymbolAddress((void**)&rsL, g_rsL);
    cudaGetSymbolAddress((void**)&cdH, g_cdH); cudaGetSymbolAddress((void**)&cdL, g_cdL);
    cudaGetSymbolAddress((void**)&pcH, g_pcH); cudaGetSymbolAddress((void**)&pcL, g_pcL);
    cudaGetSymbolAddress((void**)&rdH, g_rdH); cudaGetSymbolAddress((void**)&rdL, g_rdL);
    cudaGetSymbolAddress((void**)&prH, g_prH); cudaGetSymbolAddress((void**)&prL, g_prL);
    cudaGetSymbolAddress((void**)&w1H, g_W1H); cudaGetSymbolAddress((void**)&w1L, g_W1L);
    cudaGetSymbolAddress((void**)&w2H, g_W2H); cudaGetSymbolAddress((void**)&w2L, g_W2L);
    float *gas, *gbs, *prS, *pcS;
    cudaGetSymbolAddress((void**)&gas, g_asum);
    cudaGetSymbolAddress((void**)&gbs, g_bsum);
    cudaGetSymbolAddress((void**)&prS, g_prS); cudaGetSymbolAddress((void**)&pcS, g_pcS);

    cudaFuncSetAttribute(k_gemm<0,0,0>, cudaFuncAttributeMaxDynamicSharedMemorySize, SMEM_DYN);
    cudaFuncSetAttribute(k_gemm<1,0,1>, cudaFuncAttributeMaxDynamicSharedMemorySize, SMEM_DYN);
    cudaFuncSetAttribute(k_gemm<1,1,1>, cudaFuncAttributeMaxDynamicSharedMemorySize, SMEM_DYN);
    cudaFuncSetAttribute(k_gemm<2,0,0>, cudaFuncAttributeMaxDynamicSharedMemorySize, SMEM_DYN);

    k_wcomb_split<<<(Hn * Dn + 255) / 256, 256>>>(W1, W2);
    k_split<<<(int)((size_t)MC * Dn / 1024), 256>>>(cs, csH, csL);
    k_split<<<(int)((size_t)MR * Dn / 1024), 256>>>(rs, rsH, rsL);

    // GEMM0: exp(cs*rs^T - 64) split pairs + partial sums
    k_gemm<0,0,0><<<dim3(16, 4, Bn), 128, SMEM_DYN>>>(
        csH, csL, csH, csL, csH, csL, rsH, rsL,
        nullptr, nullptr, nullptr, nullptr, eH, eL, nullptr, nullptr,
        prS, pcS,
        Dn, Dn, Dn, LRn,
        (size_t)LCn * Dn, (size_t)LRn * Dn, (size_t)LCn * LRn, 0);

    k_merge_both<<<(MC + MR) / 256, 256>>>();

    // cd: A = Ê row-major (K=512), B = rs[k][n] via trans-ldmatrix; scale 1/asum
    k_gemm<1,0,1><<<dim3(16, 2, Bn), 128, SMEM_DYN>>>(
        eH, eL, eH, eL, eH, eL, rsH, rsL,
        gas, cs, nullptr, nullptr, cdH, cdL, pcH, pcL,
        nullptr, nullptr,
        LRn, LRn, Dn, Dn,
        (size_t)LCn * LRn, (size_t)LRn * Dn, (size_t)LCn * Dn, LCn);

    // rd: A = Ê^T via trans-ldmatrix (K=2048), B = cs[k][n] via trans-ldmatrix
    k_gemm<1,1,1><<<dim3(4, 2, Bn), 128, SMEM_DYN>>>(
        eH, eL, eH, eL, eH, eL, csH, csL,
        gbs, rs, nullptr, nullptr, rdH, rdL, prH, prL,
        nullptr, nullptr,
        LCn, LRn, Dn, Dn,
        (size_t)LCn * LRn, (size_t)LCn * Dn, (size_t)LRn * Dn, LRn);

    // cl = relu([cs|cd|cs*cd] * W1c^T + b1)
    k_gemm<2,0,0><<<dim3(MC / 128, 1, 1), 128, SMEM_DYN>>>(
        csH, csL, cdH, cdL, pcH, pcL, w1H, w1L,
        nullptr, nullptr, b1, cl, nullptr, nullptr, nullptr, nullptr,
        nullptr, nullptr,
        3 * Dn, Dn, 3 * Dn, Hn, 0, 0, 0, 0);

    // rl = relu([rs|rd|rs*rd] * W2c^T + b2)
    k_gemm<2,0,0><<<dim3(MR / 128, 1, 1), 128, SMEM_DYN>>>(
        rsH, rsL, rdH, rdL, prH, prL, w2H, w2L,
        nullptr, nullptr, b2, rl, nullptr, nullptr, nullptr, nullptr,
        nullptr, nullptr,
        3 * Dn, Dn, 3 * Dn, Hn, 0, 0, 0, 0);
}

// round 16
// speedup vs baseline: 1.0654x; 1.0096x over previous
#include <cuda_runtime.h>
#include <cuda_bf16.h>
#include <math.h>
#include <stdint.h>

#define Bn  32
#define LCn 2048
#define LRn 512
#define Dn  256
#define Hn  128
#define MC  (Bn * LCn)
#define MR  (Bn * LRn)
#define SHIFTC 64.0f

typedef __nv_bfloat16 bf16;

// -------- scratch --------
static __device__ bf16 g_EH [(size_t)Bn * LCn * LRn], g_EL [(size_t)Bn * LCn * LRn];
static __device__ bf16 g_csH[(size_t)Bn * LCn * Dn],  g_csL[(size_t)Bn * LCn * Dn];
static __device__ bf16 g_rsH[(size_t)Bn * LRn * Dn],  g_rsL[(size_t)Bn * LRn * Dn];
static __device__ bf16 g_cdH[(size_t)Bn * LCn * Dn],  g_cdL[(size_t)Bn * LCn * Dn];
static __device__ bf16 g_pcH[(size_t)Bn * LCn * Dn],  g_pcL[(size_t)Bn * LCn * Dn];
static __device__ bf16 g_rdH[(size_t)Bn * LRn * Dn],  g_rdL[(size_t)Bn * LRn * Dn];
static __device__ bf16 g_prH[(size_t)Bn * LRn * Dn],  g_prL[(size_t)Bn * LRn * Dn];
static __device__ bf16 g_W1H[Hn * 3 * Dn], g_W1L[Hn * 3 * Dn];
static __device__ bf16 g_W2H[Hn * 3 * Dn], g_W2L[Hn * 3 * Dn];
static __device__ float g_asum[MC];
static __device__ float g_bsum[MR];
static __device__ float g_prS[(size_t)Bn * 8 * LCn];     // row-sum partials
static __device__ float g_pcS[(size_t)Bn * 32 * LRn];    // col-sum partials

// ======================== helpers =============================
__device__ __forceinline__ uint32_t smem_u32(const void* p) {
    uint32_t a;
    asm("{ .reg .u64 t; cvta.to.shared.u64 t, %1; cvt.u32.u64 %0, t; }" : "=r"(a) : "l"(p));
    return a;
}

#define LDSM4(r, addr) \
    asm volatile("ldmatrix.sync.aligned.m8n8.x4.shared.b16 {%0,%1,%2,%3}, [%4];" \
        : "=r"((r)[0]), "=r"((r)[1]), "=r"((r)[2]), "=r"((r)[3]) : "r"(addr))

#define LDSM4T(r, addr) \
    asm volatile("ldmatrix.sync.aligned.m8n8.x4.trans.shared.b16 {%0,%1,%2,%3}, [%4];" \
        : "=r"((r)[0]), "=r"((r)[1]), "=r"((r)[2]), "=r"((r)[3]) : "r"(addr))

#define MMA_BF16(c, a, b0, b1) \
    asm volatile("mma.sync.aligned.m16n8k16.row.col.f32.bf16.bf16.f32 " \
        "{%0,%1,%2,%3}, {%4,%5,%6,%7}, {%8,%9}, {%0,%1,%2,%3};" \
        : "+f"((c)[0]), "+f"((c)[1]), "+f"((c)[2]), "+f"((c)[3]) \
        : "r"((a)[0]), "r"((a)[1]), "r"((a)[2]), "r"((a)[3]), "r"(b0), "r"(b1))

#define CP16(dst, src) \
    asm volatile("cp.async.cg.shared.global [%0], [%1], 16;" :: "r"(dst), "l"(src))
#define CP_COMMIT() asm volatile("cp.async.commit_group;" ::: "memory")
#define CP_WAIT(n)  asm volatile("cp.async.wait_group %0;" :: "n"(n) : "memory")

__device__ __forceinline__ void bsplit(float v, bf16& h, bf16& l) {
    h = __float2bfloat16(v);
    l = __float2bfloat16(v - __bfloat162float(h));
}

// non-trans smem tile: [rows][32 k] bf16, 64B rows; conflict-free swizzle.
__device__ __forceinline__ uint32_t toff16(int row, int u) {
    return (row << 6) + ((u ^ ((row >> 1) & 3)) << 4);
}

#define SM_AH 0
#define SM_AL 8192
#define SM_BH 16384
#define SM_BL 24576
#define STAGE_B 32768
#define SMEM_DYN (3 * STAGE_B)

// ============================================================================
// NT GEMM on pre-split bf16 pairs: C[128,128] = A[128,K]*B[128,K]^T
// (3 products HH+HL+LH).
// TRA=1: A streamed from row-major [K][M] source via ldmatrix.trans.
// TRB=1: B streamed from row-major [K][N] source via ldmatrix.trans.
// A-high fragments are pipelined across the barrier; A-low fragments are
// loaded lazily inside mmaHalf (covered by the HH+HL product groups) to
// keep register pressure off the 255 cap.
// EPI 0: emit exp(acc-SHIFT) split pairs + plain row/col partial sums.
// EPI 1: scale 1/rsum, emit split pairs + split(X*scaled).  EPI 2: relu+bias.
// ============================================================================
template<int EPI, int TRA, int TRB>
__global__ void __launch_bounds__(128, 2) k_gemm(
    const bf16* __restrict__ AH0, const bf16* __restrict__ AL0,
    const bf16* __restrict__ AH1, const bf16* __restrict__ AL1,
    const bf16* __restrict__ AH2, const bf16* __restrict__ AL2,
    const bf16* __restrict__ BH,  const bf16* __restrict__ BL,
    const float* __restrict__ rsum, const float* __restrict__ Xf,
    const float* __restrict__ bias, float* __restrict__ Cf,
    bf16* __restrict__ CoH, bf16* __restrict__ CoL,
    bf16* __restrict__ PoH, bf16* __restrict__ PoL,
    float* __restrict__ PrS, float* __restrict__ PcS,
    int K, int lda, int ldb, int ldc,
    size_t aB, size_t bB, size_t cB, int sB)
{
    extern __shared__ __align__(16) uint8_t sm[];
    const uint32_t sb = smem_u32(sm);
    const int tid = threadIdx.x;
    const int z = blockIdx.z;
    const int m0 = blockIdx.x * 128, n0 = blockIdx.y * 128;
    const bf16* aH0 = AH0 + (size_t)z * aB;
    const bf16* aL0 = AL0 + (size_t)z * aB;
    const bf16* bH  = BH  + (size_t)z * bB;
    const bf16* bL  = BL  + (size_t)z * bB;

    const int lane = tid & 31, wid = tid >> 5;
    const int wm = wid & 1, wn = wid >> 1;
    const int gid = lane >> 2, tig = lane & 3;

    float acc[4][8][4];
    #pragma unroll
    for (int a = 0; a < 4; a++)
        #pragma unroll
        for (int b = 0; b < 8; b++)
            #pragma unroll
            for (int c = 0; c < 4; c++) acc[a][b][c] = 0.f;

    const int S = K >> 5;

    auto cp_stage = [&](int buf, int kc) {
        const uint32_t tb = sb + buf * STAGE_B;
        const int k0 = kc << 5;
        if (TRA) {
            // A tile [k=32 rows][m=128], 256B rows, unit swizzle u ^= (row&7)
            #pragma unroll
            for (int i = 0; i < 4; i++) {
                int idx = tid + i * 128;
                int row = idx >> 4, u = idx & 15;
                uint32_t up = (uint32_t)(u ^ (row & 7));
                uint32_t off = row * 256 + up * 16;
                const size_t g = (size_t)(k0 + row) * lda + m0 + u * 8;
                CP16(tb + SM_AH + off, aH0 + g);
                CP16(tb + SM_AL + off, aL0 + g);
            }
        } else {
            const bf16* aH = aH0; const bf16* aL = aL0;
            int kk = k0;
            if (EPI == 2) {
                int seg = k0 >> 8; kk = k0 & 255;
                if (seg == 1) { aH = AH1; aL = AL1; }
                else if (seg == 2) { aH = AH2; aL = AL2; }
            }
            #pragma unroll
            for (int i = 0; i < 4; i++) {
                int idx = tid + i * 128;
                int row = idx >> 2, u = idx & 3;
                uint32_t off = toff16(row, u);
                const size_t g = (size_t)(m0 + row) * lda + kk + u * 8;
                CP16(tb + SM_AH + off, aH + g);
                CP16(tb + SM_AL + off, aL + g);
            }
        }
        if (TRB) {
            // B tile [k=32 rows][n=128], 256B rows, unit swizzle u ^= (row&7)
            #pragma unroll
            for (int i = 0; i < 4; i++) {
                int idx = tid + i * 128;
                int row = idx >> 4, u = idx & 15;
                uint32_t up = (uint32_t)(u ^ (row & 7));
                uint32_t off = row * 256 + up * 16;
                const size_t g = (size_t)(k0 + row) * ldb + n0 + u * 8;
                CP16(tb + SM_BH + off, bH + g);
                CP16(tb + SM_BL + off, bL + g);
            }
        } else {
            #pragma unroll
            for (int i = 0; i < 4; i++) {
                int idx = tid + i * 128;
                int row = idx >> 2, u = idx & 3;
                uint32_t off = toff16(row, u);
                const size_t g = (size_t)(n0 + row) * ldb + k0 + u * 8;
                CP16(tb + SM_BH + off, bH + g);
                CP16(tb + SM_BL + off, bL + g);
            }
        }
    };

    // A-high fragment loader for one k16 half
    auto ldAh = [&](uint32_t tb, int kb, uint32_t (&ah)[4][4]) {
        if (TRA) {
            int rowk = kb * 16 + ((lane >> 4) << 3) + (lane & 7);
            #pragma unroll
            for (int mb = 0; mb < 4; mb++) {
                int um = wm * 8 + mb * 2 + ((lane >> 3) & 1);
                uint32_t up = (uint32_t)(um ^ (rowk & 7));
                LDSM4T(ah[mb], tb + SM_AH + rowk * 256 + up * 16);
            }
        } else {
            #pragma unroll
            for (int mb = 0; mb < 4; mb++) {
                int row = wm * 64 + mb * 16 + (lane & 15);
                uint32_t off = toff16(row, kb * 2 + (lane >> 4));
                LDSM4(ah[mb], tb + SM_AH + off);
            }
        }
    };

    // A-low fragment loader (lazy, inside mmaHalf)
    auto ldAl = [&](uint32_t tb, int kb, uint32_t (&al)[4][4]) {
        if (TRA) {
            int rowk = kb * 16 + ((lane >> 4) << 3) + (lane & 7);
            #pragma unroll
            for (int mb = 0; mb < 4; mb++) {
                int um = wm * 8 + mb * 2 + ((lane >> 3) & 1);
                uint32_t up = (uint32_t)(um ^ (rowk & 7));
                LDSM4T(al[mb], tb + SM_AL + rowk * 256 + up * 16);
            }
        } else {
            #pragma unroll
            for (int mb = 0; mb < 4; mb++) {
                int row = wm * 64 + mb * 16 + (lane & 15);
                uint32_t off = toff16(row, kb * 2 + (lane >> 4));
                LDSM4(al[mb], tb + SM_AL + off);
            }
        }
    };

    // MMAs for one k16 half; al loaded lazily (covered by HH+HL groups)
    auto mmaHalf = [&](uint32_t tb, int kb, uint32_t (&ah)[4][4]) {
        uint32_t bh[4][4], bl[4][4];
        #pragma unroll
        for (int np = 0; np < 4; np++) {
            if (TRB) {
                int rowk = kb * 16 + ((lane >> 3) & 1) * 8 + (lane & 7);
                int un = wn * 8 + np * 2 + (lane >> 4);
                uint32_t up = (uint32_t)(un ^ (rowk & 7));
                uint32_t addr = tb + rowk * 256 + up * 16;
                LDSM4T(bh[np], addr + SM_BH);
                LDSM4T(bl[np], addr + SM_BL);
            } else {
                int nrow = wn * 64 + np * 16 + (lane & 7) + ((lane >> 4) << 3);
                uint32_t off = toff16(nrow, kb * 2 + ((lane >> 3) & 1));
                LDSM4(bh[np], tb + SM_BH + off);
                LDSM4(bl[np], tb + SM_BL + off);
            }
            // HH for this np
            #pragma unroll
            for (int nb = 0; nb < 2; nb++)
                #pragma unroll
                for (int mb = 0; mb < 4; mb++)
                    MMA_BF16(acc[mb][np*2+nb], ah[mb], bh[np][nb*2], bh[np][nb*2+1]);
        }
        // lazy A-low load — covered by the HL group below
        uint32_t al[4][4];
        ldAl(tb, kb, al);
        // HL
        #pragma unroll
        for (int np = 0; np < 4; np++)
            #pragma unroll
            for (int nb = 0; nb < 2; nb++)
                #pragma unroll
                for (int mb = 0; mb < 4; mb++)
                    MMA_BF16(acc[mb][np*2+nb], ah[mb], bl[np][nb*2], bl[np][nb*2+1]);
        // LH
        #pragma unroll
        for (int np = 0; np < 4; np++)
            #pragma unroll
            for (int nb = 0; nb < 2; nb++)
                #pragma unroll
                for (int mb = 0; mb < 4; mb++)
                    MMA_BF16(acc[mb][np*2+nb], al[mb], bh[np][nb*2], bh[np][nb*2+1]);
    };

    uint32_t A0h[4][4], A1h[4][4];

    cp_stage(0, 0); CP_COMMIT();
    if (S > 1) cp_stage(1, 1);
    CP_COMMIT();
    CP_WAIT(1);
    __syncthreads();
    ldAh(sb, 0, A0h);

    for (int s = 0; s < S; s++) {
        const uint32_t tb = sb + (s % 3) * STAGE_B;
        ldAh(tb, 1, A1h);
        mmaHalf(tb, 0, A0h);

        CP_WAIT(0);
        __syncthreads();
        if (s + 2 < S) cp_stage((s + 2) % 3, s + 2);
        CP_COMMIT();
        if (s + 1 < S) {
            const uint32_t tbn = sb + ((s + 1) % 3) * STAGE_B;
            ldAh(tbn, 0, A0h);
        }
        mmaHalf(tb, 1, A1h);
    }

    // ---- epilogue ----
    if (EPI == 0) {
        float rsum8[8];
        float csum16[16];
        #pragma unroll
        for (int j = 0; j < 8; j++) rsum8[j] = 0.f;
        #pragma unroll
        for (int q = 0; q < 16; q++) csum16[q] = 0.f;
        bf16* cH = CoH + (size_t)z * cB; bf16* cL = CoL + (size_t)z * cB;
        #pragma unroll
        for (int mb = 0; mb < 4; mb++) {
            int r0 = m0 + wm * 64 + mb * 16 + gid;
            int r1 = r0 + 8;
            #pragma unroll
            for (int nb = 0; nb < 8; nb++) {
                int col = n0 + wn * 64 + nb * 8 + tig * 2;
                float p0 = __expf(acc[mb][nb][0] - SHIFTC);
                float p1 = __expf(acc[mb][nb][1] - SHIFTC);
                float p2 = __expf(acc[mb][nb][2] - SHIFTC);
                float p3 = __expf(acc[mb][nb][3] - SHIFTC);
                size_t o0 = (size_t)r0 * ldc + col, o1 = (size_t)r1 * ldc + col;
                bf16 h, l; __nv_bfloat162 hv, lv;
                bsplit(p0, h, l); hv.x = h; lv.x = l;
                bsplit(p1, h, l); hv.y = h; lv.y = l;
                *(__nv_bfloat162*)(cH + o0) = hv; *(__nv_bfloat162*)(cL + o0) = lv;
                bsplit(p2, h, l); hv.x = h; lv.x = l;
                bsplit(p3, h, l); hv.y = h; lv.y = l;
                *(__nv_bfloat162*)(cH + o1) = hv; *(__nv_bfloat162*)(cL + o1) = lv;
                rsum8[mb*2]   += p0 + p1;
                rsum8[mb*2+1] += p2 + p3;
                csum16[nb*2]   += p0 + p2;
                csum16[nb*2+1] += p1 + p3;
            }
        }
        #pragma unroll
        for (int o = 1; o <= 2; o <<= 1)
            #pragma unroll
            for (int j = 0; j < 8; j++)
                rsum8[j] += __shfl_xor_sync(0xffffffffu, rsum8[j], o);
        if (tig == 0) {
            #pragma unroll
            for (int j = 0; j < 8; j++) {
                int row = m0 + wm * 64 + (j >> 1) * 16 + (j & 1) * 8 + gid;
                size_t o = ((size_t)z * 8 + blockIdx.y * 2 + wn) * (size_t)LCn + row;
                PrS[o] = rsum8[j];
            }
        }
        #pragma unroll
        for (int o = 4; o <= 16; o <<= 1)
            #pragma unroll
            for (int q = 0; q < 16; q++)
                csum16[q] += __shfl_xor_sync(0xffffffffu, csum16[q], o);
        if (gid == 0) {
            #pragma unroll
            for (int q = 0; q < 16; q++) {
                int col = n0 + wn * 64 + (q >> 1) * 8 + tig * 2 + (q & 1);
                size_t o = ((size_t)z * 32 + blockIdx.x * 2 + wm) * (size_t)LRn + col;
                PcS[o] = csum16[q];
            }
        }
        return;
    }

    #pragma unroll
    for (int mb = 0; mb < 4; mb++) {
        int r0 = m0 + wm * 64 + mb * 16 + gid;
        int r1 = r0 + 8;
        float s0 = 1.f, s1 = 1.f;
        if (EPI == 1) {
            s0 = 1.0f / rsum[(size_t)z * sB + r0];
            s1 = 1.0f / rsum[(size_t)z * sB + r1];
        }
        #pragma unroll
        for (int nb = 0; nb < 8; nb++) {
            int col = n0 + wn * 64 + nb * 8 + tig * 2;
            float c0 = acc[mb][nb][0], c1 = acc[mb][nb][1];
            float c2 = acc[mb][nb][2], c3 = acc[mb][nb][3];
            if (EPI == 2) {
                float b0v = bias[col], b1v = bias[col + 1];
                float* C = Cf;
                *(float2*)(C + (size_t)r0 * ldc + col) =
                    make_float2(fmaxf(c0 + b0v, 0.f), fmaxf(c1 + b1v, 0.f));
                *(float2*)(C + (size_t)r1 * ldc + col) =
                    make_float2(fmaxf(c2 + b0v, 0.f), fmaxf(c3 + b1v, 0.f));
            } else {
                c0 *= s0; c1 *= s0; c2 *= s1; c3 *= s1;
                const float* X = Xf + (size_t)z * cB;
                bf16* cH = CoH + (size_t)z * cB; bf16* cL = CoL + (size_t)z * cB;
                bf16* pH = PoH + (size_t)z * cB; bf16* pL = PoL + (size_t)z * cB;
                size_t o0 = (size_t)r0 * ldc + col, o1 = (size_t)r1 * ldc + col;
                float2 x0 = *(const float2*)(X + o0);
                float2 x1 = *(const float2*)(X + o1);
                bf16 h, l; __nv_bfloat162 hv, lv;
                bsplit(c0, h, l); hv.x = h; lv.x = l;
                bsplit(c1, h, l); hv.y = h; lv.y = l;
                *(__nv_bfloat162*)(cH + o0) = hv; *(__nv_bfloat162*)(cL + o0) = lv;
                bsplit(c2, h, l); hv.x = h; lv.x = l;
                bsplit(c3, h, l); hv.y = h; lv.y = l;
                *(__nv_bfloat162*)(cH + o1) = hv; *(__nv_bfloat162*)(cL + o1) = lv;
                bsplit(x0.x * c0, h, l); hv.x = h; lv.x = l;
                bsplit(x0.y * c1, h, l); hv.y = h; lv.y = l;
                *(__nv_bfloat162*)(pH + o0) = hv; *(__nv_bfloat162*)(pL + o0) = lv;
                bsplit(x1.x * c2, h, l); hv.x = h; lv.x = l;
                bsplit(x1.y * c3, h, l); hv.y = h; lv.y = l;
                *(__nv_bfloat162*)(pH + o1) = hv; *(__nv_bfloat162*)(pL + o1) = lv;
            }
        }
    }
}

// ============================================================================
// Sum merges (plain adds — shift-invariant softmax needs no max)
// ============================================================================
__global__ void k_merge_both() {
    int idx = blockIdx.x * 256 + threadIdx.x;
    if (idx < MC) {
        int b = idx >> 11, c = idx & (LCn - 1);
        float s = 0.f;
        #pragma unroll
        for (int j = 0; j < 8; j++)
            s += g_prS[((size_t)b * 8 + j) * LCn + c];
        g_asum[idx] = s;
    } else {
        int i2 = idx - MC;
        int b = i2 >> 9, r = i2 & (LRn - 1);
        float s = 0.f;
        #pragma unroll
        for (int j = 0; j < 32; j++)
            s += g_pcS[((size_t)b * 32 + j) * LRn + r];
        g_bsum[i2] = s;
    }
}

// ============================================================================
// Elementwise split
// ============================================================================
__global__ void k_split(const float* __restrict__ src, bf16* __restrict__ H,
                        bf16* __restrict__ L) {
    size_t e4 = ((size_t)blockIdx.x * 256 + threadIdx.x) * 4;
    float4 v = *(const float4*)(src + e4);
    bf16 h, l; __nv_bfloat162 h01, h23, l01, l23;
    bsplit(v.x, h, l); h01.x = h; l01.x = l;
    bsplit(v.y, h, l); h01.y = h; l01.y = l;
    bsplit(v.z, h, l); h23.x = h; l23.x = l;
    bsplit(v.w, h, l); h23.y = h; l23.y = l;
    *(__nv_bfloat162*)(H + e4) = h01; *(__nv_bfloat162*)(H + e4 + 2) = h23;
    *(__nv_bfloat162*)(L + e4) = l01; *(__nv_bfloat162*)(L + e4 + 2) = l23;
}

__global__ void k_wcomb_split(const float* __restrict__ W1, const float* __restrict__ W2) {
    int i = blockIdx.x * 256 + threadIdx.x;
    if (i >= Hn * Dn) return;
    int hh = i >> 8, d = i & (Dn - 1);
    const float* w1 = W1 + (size_t)hh * 4 * Dn;
    const float* w2 = W2 + (size_t)hh * 4 * Dn;
    float v; bf16 h, l;
    size_t base = (size_t)hh * 3 * Dn + d;
    v = w1[d] + w1[2 * Dn + d];      bsplit(v, h, l); g_W1H[base] = h;          g_W1L[base] = l;
    v = w1[Dn + d] - w1[2 * Dn + d]; bsplit(v, h, l); g_W1H[base + Dn] = h;     g_W1L[base + Dn] = l;
    v = w1[3 * Dn + d];              bsplit(v, h, l); g_W1H[base + 2 * Dn] = h; g_W1L[base + 2 * Dn] = l;
    v = w2[d] + w2[2 * Dn + d];      bsplit(v, h, l); g_W2H[base] = h;          g_W2L[base] = l;
    v = w2[Dn + d] - w2[2 * Dn + d]; bsplit(v, h, l); g_W2H[base + Dn] = h;     g_W2L[base + Dn] = l;
    v = w2[3 * Dn + d];              bsplit(v, h, l); g_W2H[base + 2 * Dn] = h; g_W2L[base + 2 * Dn] = l;
}

// ============================================================================
extern "C" void kernel_launch(void* const* d_in, const int* in_sizes, int n_in,
                              void* d_out, int out_size) {
    const float* cs = (const float*)d_in[0];
    const float* rs = (const float*)d_in[1];
    const float* W1 = (const float*)d_in[2];
    const float* b1 = (const float*)d_in[3];
    const float* W2 = (const float*)d_in[4];
    const float* b2 = (const float*)d_in[5];
    float* cl = (float*)d_out;
    float* rl = cl + (size_t)MC * Hn;

    bf16 *eH, *eL, *csH, *csL, *rsH, *rsL;
    bf16 *cdH, *cdL, *pcH, *pcL, *rdH, *rdL, *prH, *prL, *w1H, *w1L, *w2H, *w2L;
    cudaGetSymbolAddress((void**)&eH, g_EH);   cudaGetSymbolAddress((void**)&eL, g_EL);
    cudaGetSymbolAddress((void**)&csH, g_csH); cudaGetSymbolAddress((void**)&csL, g_csL);
    cudaGetSymbolAddress((void**)&rsH, g_rsH); cudaGetSymbolAddress((void**)&rsL, g_rsL);
    cudaGetSymbolAddress((void**)&cdH, g_cdH); cudaGetSymbolAddress((void**)&cdL, g_cdL);
    cudaGetSymbolAddress((void**)&pcH, g_pcH); cudaGetSymbolAddress((void**)&pcL, g_pcL);
    cudaGetSymbolAddress((void**)&rdH, g_rdH); cudaGetSymbolAddress((void**)&rdL, g_rdL);
    cudaGetSymbolAddress((void**)&prH, g_prH); cudaGetSymbolAddress((void**)&prL, g_prL);
    cudaGetSymbolAddress((void**)&w1H, g_W1H); cudaGetSymbolAddress((void**)&w1L, g_W1L);
    cudaGetSymbolAddress((void**)&w2H, g_W2H); cudaGetSymbolAddress((void**)&w2L, g_W2L);
    float *gas, *gbs, *prS, *pcS;
    cudaGetSymbolAddress((void**)&gas, g_asum);
    cudaGetSymbolAddress((void**)&gbs, g_bsum);
    cudaGetSymbolAddress((void**)&prS, g_prS); cudaGetSymbolAddress((void**)&pcS, g_pcS);

    cudaFuncSetAttribute(k_gemm<0,0,0>, cudaFuncAttributeMaxDynamicSharedMemorySize, SMEM_DYN);
    cudaFuncSetAttribute(k_gemm<1,0,1>, cudaFuncAttributeMaxDynamicSharedMemorySize, SMEM_DYN);
    cudaFuncSetAttribute(k_gemm<1,1,1>, cudaFuncAttributeMaxDynamicSharedMemorySize, SMEM_DYN);
    cudaFuncSetAttribute(k_gemm<2,0,0>, cudaFuncAttributeMaxDynamicSharedMemorySize, SMEM_DYN);

    k_wcomb_split<<<(Hn * Dn + 255) / 256, 256>>>(W1, W2);
    k_split<<<(int)((size_t)MC * Dn / 1024), 256>>>(cs, csH, csL);
    k_split<<<(int)((size_t)MR * Dn / 1024), 256>>>(rs, rsH, rsL);

    // GEMM0: exp(cs*rs^T - 64) split pairs + partial sums
    k_gemm<0,0,0><<<dim3(16, 4, Bn), 128, SMEM_DYN>>>(
        csH, csL, csH, csL, csH, csL, rsH, rsL,
        nullptr, nullptr, nullptr, nullptr, eH, eL, nullptr, nullptr,
        prS, pcS,
        Dn, Dn, Dn, LRn,
        (size_t)LCn * Dn, (size_t)LRn * Dn, (size_t)LCn * LRn, 0);

    k_merge_both<<<(MC + MR) / 256, 256>>>();

    // cd: A = Ê row-major (K=512), B = rs[k][n] via trans-ldmatrix; scale 1/asum
    k_gemm<1,0,1><<<dim3(16, 2, Bn), 128, SMEM_DYN>>>(
        eH, eL, eH, eL, eH, eL, rsH, rsL,
        gas, cs, nullptr, nullptr, cdH, cdL, pcH, pcL,
        nullptr, nullptr,
        LRn, LRn, Dn, Dn,
        (size_t)LCn * LRn, (size_t)LRn * Dn, (size_t)LCn * Dn, LCn);

    // rd: A = Ê^T via trans-ldmatrix (K=2048), B = cs[k][n] via trans-ldmatrix
    k_gemm<1,1,1><<<dim3(4, 2, Bn), 128, SMEM_DYN>>>(
        eH, eL, eH, eL, eH, eL, csH, csL,
        gbs, rs, nullptr, nullptr, rdH, rdL, prH, prL,
        nullptr, nullptr,
        LCn, LRn, Dn, Dn,
        (size_t)LCn * LRn, (size_t)LCn * Dn, (size_t)LRn * Dn, LRn);

    // cl = relu([cs|cd|cs*cd] * W1c^T + b1)
    k_gemm<2,0,0><<<dim3(MC / 128, 1, 1), 128, SMEM_DYN>>>(
        csH, csL, cdH, cdL, pcH, pcL, w1H, w1L,
        nullptr, nullptr, b1, cl, nullptr, nullptr, nullptr, nullptr,
        nullptr, nullptr,
        3 * Dn, Dn, 3 * Dn, Hn, 0, 0, 0, 0);

    // rl = relu([rs|rd|rs*rd] * W2c^T + b2)
    k_gemm<2,0,0><<<dim3(MR / 128, 1, 1), 128, SMEM_DYN>>>(
        rsH, rsL, rdH, rdL, prH, prL, w2H, w2L,
        nullptr, nullptr, b2, rl, nullptr, nullptr, nullptr, nullptr,
        nullptr, nullptr,
        3 * Dn, Dn, 3 * Dn, Hn, 0, 0, 0, 0);
}

// round 17
// speedup vs baseline: 1.0683x; 1.0027x over previous
#include <cuda_runtime.h>
#include <cuda_bf16.h>
#include <math.h>
#include <stdint.h>

#define Bn  32
#define LCn 2048
#define LRn 512
#define Dn  256
#define Hn  128
#define MC  (Bn * LCn)
#define MR  (Bn * LRn)
#define SHIFTC 64.0f

typedef __nv_bfloat16 bf16;

// -------- scratch --------
static __device__ bf16 g_EH [(size_t)Bn * LCn * LRn], g_EL [(size_t)Bn * LCn * LRn];
static __device__ bf16 g_csH[(size_t)Bn * LCn * Dn],  g_csL[(size_t)Bn * LCn * Dn];
static __device__ bf16 g_rsH[(size_t)Bn * LRn * Dn],  g_rsL[(size_t)Bn * LRn * Dn];
static __device__ bf16 g_cdH[(size_t)Bn * LCn * Dn],  g_cdL[(size_t)Bn * LCn * Dn];
static __device__ bf16 g_pcH[(size_t)Bn * LCn * Dn],  g_pcL[(size_t)Bn * LCn * Dn];
static __device__ bf16 g_rdH[(size_t)Bn * LRn * Dn],  g_rdL[(size_t)Bn * LRn * Dn];
static __device__ bf16 g_prH[(size_t)Bn * LRn * Dn],  g_prL[(size_t)Bn * LRn * Dn];
static __device__ bf16 g_W1H[Hn * 3 * Dn], g_W1L[Hn * 3 * Dn];
static __device__ bf16 g_W2H[Hn * 3 * Dn], g_W2L[Hn * 3 * Dn];
static __device__ float g_asum[MC];
static __device__ float g_bsum[MR];
static __device__ float g_prS[(size_t)Bn * 8 * LCn];     // row-sum partials
static __device__ float g_pcS[(size_t)Bn * 32 * LRn];    // col-sum partials

// ======================== helpers =============================
__device__ __forceinline__ uint32_t smem_u32(const void* p) {
    uint32_t a;
    asm("{ .reg .u64 t; cvta.to.shared.u64 t, %1; cvt.u32.u64 %0, t; }" : "=r"(a) : "l"(p));
    return a;
}

#define LDSM4(r, addr) \
    asm volatile("ldmatrix.sync.aligned.m8n8.x4.shared.b16 {%0,%1,%2,%3}, [%4];" \
        : "=r"((r)[0]), "=r"((r)[1]), "=r"((r)[2]), "=r"((r)[3]) : "r"(addr))

#define LDSM4T(r, addr) \
    asm volatile("ldmatrix.sync.aligned.m8n8.x4.trans.shared.b16 {%0,%1,%2,%3}, [%4];" \
        : "=r"((r)[0]), "=r"((r)[1]), "=r"((r)[2]), "=r"((r)[3]) : "r"(addr))

#define MMA_BF16(c, a, b0, b1) \
    asm volatile("mma.sync.aligned.m16n8k16.row.col.f32.bf16.bf16.f32 " \
        "{%0,%1,%2,%3}, {%4,%5,%6,%7}, {%8,%9}, {%0,%1,%2,%3};" \
        : "+f"((c)[0]), "+f"((c)[1]), "+f"((c)[2]), "+f"((c)[3]) \
        : "r"((a)[0]), "r"((a)[1]), "r"((a)[2]), "r"((a)[3]), "r"(b0), "r"(b1))

#define CP16(dst, src) \
    asm volatile("cp.async.cg.shared.global [%0], [%1], 16;" :: "r"(dst), "l"(src))
#define CP_COMMIT() asm volatile("cp.async.commit_group;" ::: "memory")
#define CP_WAIT(n)  asm volatile("cp.async.wait_group %0;" :: "n"(n) : "memory")

__device__ __forceinline__ void bsplit(float v, bf16& h, bf16& l) {
    h = __float2bfloat16(v);
    l = __float2bfloat16(v - __bfloat162float(h));
}

// non-trans smem tile: [rows][32 k] bf16, 64B rows; conflict-free swizzle.
__device__ __forceinline__ uint32_t toff16(int row, int u) {
    return (row << 6) + ((u ^ ((row >> 1) & 3)) << 4);
}

#define SM_AH 0
#define SM_AL 8192
#define SM_BH 16384
#define SM_BL 24576
#define STAGE_B 32768
#define SMEM_DYN (3 * STAGE_B)

// ============================================================================
// NT GEMM on pre-split bf16 pairs: C[128,128] = A[128,K]*B[128,K]^T
// (3 products HH+HL+LH).
// TRA=1: A streamed from row-major [K][M] source via ldmatrix.trans.
// TRB=1: B streamed from row-major [K][N] source via ldmatrix.trans.
// A-high pipelined across the barrier; A-low lazy per half; B fragments
// double-buffered one np ahead so every LDSM is covered by ~24 MMAs.
// EPI 0: emit exp(acc-SHIFT) split pairs + plain row/col partial sums.
// EPI 1: scale 1/rsum, emit split pairs + split(X*scaled).  EPI 2: relu+bias.
// ============================================================================
template<int EPI, int TRA, int TRB>
__global__ void __launch_bounds__(128, 2) k_gemm(
    const bf16* __restrict__ AH0, const bf16* __restrict__ AL0,
    const bf16* __restrict__ AH1, const bf16* __restrict__ AL1,
    const bf16* __restrict__ AH2, const bf16* __restrict__ AL2,
    const bf16* __restrict__ BH,  const bf16* __restrict__ BL,
    const float* __restrict__ rsum, const float* __restrict__ Xf,
    const float* __restrict__ bias, float* __restrict__ Cf,
    bf16* __restrict__ CoH, bf16* __restrict__ CoL,
    bf16* __restrict__ PoH, bf16* __restrict__ PoL,
    float* __restrict__ PrS, float* __restrict__ PcS,
    int K, int lda, int ldb, int ldc,
    size_t aB, size_t bB, size_t cB, int sB)
{
    extern __shared__ __align__(16) uint8_t sm[];
    const uint32_t sb = smem_u32(sm);
    const int tid = threadIdx.x;
    const int z = blockIdx.z;
    const int m0 = blockIdx.x * 128, n0 = blockIdx.y * 128;
    const bf16* aH0 = AH0 + (size_t)z * aB;
    const bf16* aL0 = AL0 + (size_t)z * aB;
    const bf16* bH  = BH  + (size_t)z * bB;
    const bf16* bL  = BL  + (size_t)z * bB;

    const int lane = tid & 31, wid = tid >> 5;
    const int wm = wid & 1, wn = wid >> 1;
    const int gid = lane >> 2, tig = lane & 3;

    float acc[4][8][4];
    #pragma unroll
    for (int a = 0; a < 4; a++)
        #pragma unroll
        for (int b = 0; b < 8; b++)
            #pragma unroll
            for (int c = 0; c < 4; c++) acc[a][b][c] = 0.f;

    const int S = K >> 5;

    auto cp_stage = [&](int buf, int kc) {
        const uint32_t tb = sb + buf * STAGE_B;
        const int k0 = kc << 5;
        if (TRA) {
            // A tile [k=32 rows][m=128], 256B rows, unit swizzle u ^= (row&7)
            #pragma unroll
            for (int i = 0; i < 4; i++) {
                int idx = tid + i * 128;
                int row = idx >> 4, u = idx & 15;
                uint32_t up = (uint32_t)(u ^ (row & 7));
                uint32_t off = row * 256 + up * 16;
                const size_t g = (size_t)(k0 + row) * lda + m0 + u * 8;
                CP16(tb + SM_AH + off, aH0 + g);
                CP16(tb + SM_AL + off, aL0 + g);
            }
        } else {
            const bf16* aH = aH0; const bf16* aL = aL0;
            int kk = k0;
            if (EPI == 2) {
                int seg = k0 >> 8; kk = k0 & 255;
                if (seg == 1) { aH = AH1; aL = AL1; }
                else if (seg == 2) { aH = AH2; aL = AL2; }
            }
            #pragma unroll
            for (int i = 0; i < 4; i++) {
                int idx = tid + i * 128;
                int row = idx >> 2, u = idx & 3;
                uint32_t off = toff16(row, u);
                const size_t g = (size_t)(m0 + row) * lda + kk + u * 8;
                CP16(tb + SM_AH + off, aH + g);
                CP16(tb + SM_AL + off, aL + g);
            }
        }
        if (TRB) {
            // B tile [k=32 rows][n=128], 256B rows, unit swizzle u ^= (row&7)
            #pragma unroll
            for (int i = 0; i < 4; i++) {
                int idx = tid + i * 128;
                int row = idx >> 4, u = idx & 15;
                uint32_t up = (uint32_t)(u ^ (row & 7));
                uint32_t off = row * 256 + up * 16;
                const size_t g = (size_t)(k0 + row) * ldb + n0 + u * 8;
                CP16(tb + SM_BH + off, bH + g);
                CP16(tb + SM_BL + off, bL + g);
            }
        } else {
            #pragma unroll
            for (int i = 0; i < 4; i++) {
                int idx = tid + i * 128;
                int row = idx >> 2, u = idx & 3;
                uint32_t off = toff16(row, u);
                const size_t g = (size_t)(n0 + row) * ldb + k0 + u * 8;
                CP16(tb + SM_BH + off, bH + g);
                CP16(tb + SM_BL + off, bL + g);
            }
        }
    };

    // A-high fragment loader for one k16 half
    auto ldAh = [&](uint32_t tb, int kb, uint32_t (&ah)[4][4]) {
        if (TRA) {
            int rowk = kb * 16 + ((lane >> 4) << 3) + (lane & 7);
            #pragma unroll
            for (int mb = 0; mb < 4; mb++) {
                int um = wm * 8 + mb * 2 + ((lane >> 3) & 1);
                uint32_t up = (uint32_t)(um ^ (rowk & 7));
                LDSM4T(ah[mb], tb + SM_AH + rowk * 256 + up * 16);
            }
        } else {
            #pragma unroll
            for (int mb = 0; mb < 4; mb++) {
                int row = wm * 64 + mb * 16 + (lane & 15);
                uint32_t off = toff16(row, kb * 2 + (lane >> 4));
                LDSM4(ah[mb], tb + SM_AH + off);
            }
        }
    };

    // A-low fragment loader (lazy, inside mmaHalf)
    auto ldAl = [&](uint32_t tb, int kb, uint32_t (&al)[4][4]) {
        if (TRA) {
            int rowk = kb * 16 + ((lane >> 4) << 3) + (lane & 7);
            #pragma unroll
            for (int mb = 0; mb < 4; mb++) {
                int um = wm * 8 + mb * 2 + ((lane >> 3) & 1);
                uint32_t up = (uint32_t)(um ^ (rowk & 7));
                LDSM4T(al[mb], tb + SM_AL + rowk * 256 + up * 16);
            }
        } else {
            #pragma unroll
            for (int mb = 0; mb < 4; mb++) {
                int row = wm * 64 + mb * 16 + (lane & 15);
                uint32_t off = toff16(row, kb * 2 + (lane >> 4));
                LDSM4(al[mb], tb + SM_AL + off);
            }
        }
    };

    // B fragment loader for one np block
    auto ldB = [&](uint32_t tb, int kb, int np, uint32_t (&bh)[4], uint32_t (&bl)[4]) {
        if (TRB) {
            int rowk = kb * 16 + ((lane >> 3) & 1) * 8 + (lane & 7);
            int un = wn * 8 + np * 2 + (lane >> 4);
            uint32_t up = (uint32_t)(un ^ (rowk & 7));
            uint32_t addr = tb + rowk * 256 + up * 16;
            LDSM4T(bh, addr + SM_BH);
            LDSM4T(bl, addr + SM_BL);
        } else {
            int nrow = wn * 64 + np * 16 + (lane & 7) + ((lane >> 4) << 3);
            uint32_t off = toff16(nrow, kb * 2 + ((lane >> 3) & 1));
            LDSM4(bh, tb + SM_BH + off);
            LDSM4(bl, tb + SM_BL + off);
        }
    };

    // MMAs for one k16 half: per-np complete (HH,HL,LH), B one np ahead.
    auto mmaHalf = [&](uint32_t tb, int kb, uint32_t (&ah)[4][4]) {
        uint32_t b0h[4], b0l[4], b1h[4], b1l[4];
        ldB(tb, kb, 0, b0h, b0l);
        uint32_t al[4][4];
        ldAl(tb, kb, al);                 // consumed at LH(0), after 16 MMAs
        #pragma unroll
        for (int np = 0; np < 4; np++) {
            uint32_t (&bh)[4] = (np & 1) ? b1h : b0h;
            uint32_t (&bl)[4] = (np & 1) ? b1l : b0l;
            if (np < 3) {
                uint32_t (&nh)[4] = (np & 1) ? b0h : b1h;
                uint32_t (&nl)[4] = (np & 1) ? b0l : b1l;
                ldB(tb, kb, np + 1, nh, nl);   // covered by 24 MMAs below
            }
            #pragma unroll
            for (int nb = 0; nb < 2; nb++)
                #pragma unroll
                for (int mb = 0; mb < 4; mb++)
                    MMA_BF16(acc[mb][np*2+nb], ah[mb], bh[nb*2], bh[nb*2+1]);
            #pragma unroll
            for (int nb = 0; nb < 2; nb++)
                #pragma unroll
                for (int mb = 0; mb < 4; mb++)
                    MMA_BF16(acc[mb][np*2+nb], ah[mb], bl[nb*2], bl[nb*2+1]);
            #pragma unroll
            for (int nb = 0; nb < 2; nb++)
                #pragma unroll
                for (int mb = 0; mb < 4; mb++)
                    MMA_BF16(acc[mb][np*2+nb], al[mb], bh[nb*2], bh[nb*2+1]);
        }
    };

    uint32_t A0h[4][4], A1h[4][4];

    cp_stage(0, 0); CP_COMMIT();
    if (S > 1) cp_stage(1, 1);
    CP_COMMIT();
    CP_WAIT(1);
    __syncthreads();
    ldAh(sb, 0, A0h);

    for (int s = 0; s < S; s++) {
        const uint32_t tb = sb + (s % 3) * STAGE_B;
        ldAh(tb, 1, A1h);
        mmaHalf(tb, 0, A0h);

        CP_WAIT(0);
        __syncthreads();
        if (s + 2 < S) cp_stage((s + 2) % 3, s + 2);
        CP_COMMIT();
        if (s + 1 < S) {
            const uint32_t tbn = sb + ((s + 1) % 3) * STAGE_B;
            ldAh(tbn, 0, A0h);
        }
        mmaHalf(tb, 1, A1h);
    }

    // ---- epilogue ----
    if (EPI == 0) {
        float rsum8[8];
        float csum16[16];
        #pragma unroll
        for (int j = 0; j < 8; j++) rsum8[j] = 0.f;
        #pragma unroll
        for (int q = 0; q < 16; q++) csum16[q] = 0.f;
        bf16* cH = CoH + (size_t)z * cB; bf16* cL = CoL + (size_t)z * cB;
        #pragma unroll
        for (int mb = 0; mb < 4; mb++) {
            int r0 = m0 + wm * 64 + mb * 16 + gid;
            int r1 = r0 + 8;
            #pragma unroll
            for (int nb = 0; nb < 8; nb++) {
                int col = n0 + wn * 64 + nb * 8 + tig * 2;
                float p0 = __expf(acc[mb][nb][0] - SHIFTC);
                float p1 = __expf(acc[mb][nb][1] - SHIFTC);
                float p2 = __expf(acc[mb][nb][2] - SHIFTC);
                float p3 = __expf(acc[mb][nb][3] - SHIFTC);
                size_t o0 = (size_t)r0 * ldc + col, o1 = (size_t)r1 * ldc + col;
                bf16 h, l; __nv_bfloat162 hv, lv;
                bsplit(p0, h, l); hv.x = h; lv.x = l;
                bsplit(p1, h, l); hv.y = h; lv.y = l;
                *(__nv_bfloat162*)(cH + o0) = hv; *(__nv_bfloat162*)(cL + o0) = lv;
                bsplit(p2, h, l); hv.x = h; lv.x = l;
                bsplit(p3, h, l); hv.y = h; lv.y = l;
                *(__nv_bfloat162*)(cH + o1) = hv; *(__nv_bfloat162*)(cL + o1) = lv;
                rsum8[mb*2]   += p0 + p1;
                rsum8[mb*2+1] += p2 + p3;
                csum16[nb*2]   += p0 + p2;
                csum16[nb*2+1] += p1 + p3;
            }
        }
        #pragma unroll
        for (int o = 1; o <= 2; o <<= 1)
            #pragma unroll
            for (int j = 0; j < 8; j++)
                rsum8[j] += __shfl_xor_sync(0xffffffffu, rsum8[j], o);
        if (tig == 0) {
            #pragma unroll
            for (int j = 0; j < 8; j++) {
                int row = m0 + wm * 64 + (j >> 1) * 16 + (j & 1) * 8 + gid;
                size_t o = ((size_t)z * 8 + blockIdx.y * 2 + wn) * (size_t)LCn + row;
                PrS[o] = rsum8[j];
            }
        }
        #pragma unroll
        for (int o = 4; o <= 16; o <<= 1)
            #pragma unroll
            for (int q = 0; q < 16; q++)
                csum16[q] += __shfl_xor_sync(0xffffffffu, csum16[q], o);
        if (gid == 0) {
            #pragma unroll
            for (int q = 0; q < 16; q++) {
                int col = n0 + wn * 64 + (q >> 1) * 8 + tig * 2 + (q & 1);
                size_t o = ((size_t)z * 32 + blockIdx.x * 2 + wm) * (size_t)LRn + col;
                PcS[o] = csum16[q];
            }
        }
        return;
    }

    #pragma unroll
    for (int mb = 0; mb < 4; mb++) {
        int r0 = m0 + wm * 64 + mb * 16 + gid;
        int r1 = r0 + 8;
        float s0 = 1.f, s1 = 1.f;
        if (EPI == 1) {
            s0 = 1.0f / rsum[(size_t)z * sB + r0];
            s1 = 1.0f / rsum[(size_t)z * sB + r1];
        }
        #pragma unroll
        for (int nb = 0; nb < 8; nb++) {
            int col = n0 + wn * 64 + nb * 8 + tig * 2;
            float c0 = acc[mb][nb][0], c1 = acc[mb][nb][1];
            float c2 = acc[mb][nb][2], c3 = acc[mb][nb][3];
            if (EPI == 2) {
                float b0v = bias[col], b1v = bias[col + 1];
                float* C = Cf;
                *(float2*)(C + (size_t)r0 * ldc + col) =
                    make_float2(fmaxf(c0 + b0v, 0.f), fmaxf(c1 + b1v, 0.f));
                *(float2*)(C + (size_t)r1 * ldc + col) =
                    make_float2(fmaxf(c2 + b0v, 0.f), fmaxf(c3 + b1v, 0.f));
            } else {
                c0 *= s0; c1 *= s0; c2 *= s1; c3 *= s1;
                const float* X = Xf + (size_t)z * cB;
                bf16* cH = CoH + (size_t)z * cB; bf16* cL = CoL + (size_t)z * cB;
                bf16* pH = PoH + (size_t)z * cB; bf16* pL = PoL + (size_t)z * cB;
                size_t o0 = (size_t)r0 * ldc + col, o1 = (size_t)r1 * ldc + col;
                float2 x0 = *(const float2*)(X + o0);
                float2 x1 = *(const float2*)(X + o1);
                bf16 h, l; __nv_bfloat162 hv, lv;
                bsplit(c0, h, l); hv.x = h; lv.x = l;
                bsplit(c1, h, l); hv.y = h; lv.y = l;
                *(__nv_bfloat162*)(cH + o0) = hv; *(__nv_bfloat162*)(cL + o0) = lv;
                bsplit(c2, h, l); hv.x = h; lv.x = l;
                bsplit(c3, h, l); hv.y = h; lv.y = l;
                *(__nv_bfloat162*)(cH + o1) = hv; *(__nv_bfloat162*)(cL + o1) = lv;
                bsplit(x0.x * c0, h, l); hv.x = h; lv.x = l;
                bsplit(x0.y * c1, h, l); hv.y = h; lv.y = l;
                *(__nv_bfloat162*)(pH + o0) = hv; *(__nv_bfloat162*)(pL + o0) = lv;
                bsplit(x1.x * c2, h, l); hv.x = h; lv.x = l;
                bsplit(x1.y * c3, h, l); hv.y = h; lv.y = l;
                *(__nv_bfloat162*)(pH + o1) = hv; *(__nv_bfloat162*)(pL + o1) = lv;
            }
        }
    }
}

// ============================================================================
// Sum merges (plain adds — shift-invariant softmax needs no max)
// ============================================================================
__global__ void k_merge_both() {
    int idx = blockIdx.x * 256 + threadIdx.x;
    if (idx < MC) {
        int b = idx >> 11, c = idx & (LCn - 1);
        float s = 0.f;
        #pragma unroll
        for (int j = 0; j < 8; j++)
            s += g_prS[((size_t)b * 8 + j) * LCn + c];
        g_asum[idx] = s;
    } else {
        int i2 = idx - MC;
        int b = i2 >> 9, r = i2 & (LRn - 1);
        float s = 0.f;
        #pragma unroll
        for (int j = 0; j < 32; j++)
            s += g_pcS[((size_t)b * 32 + j) * LRn + r];
        g_bsum[i2] = s;
    }
}

// ============================================================================
// Elementwise split
// ============================================================================
__global__ void k_split(const float* __restrict__ src, bf16* __restrict__ H,
                        bf16* __restrict__ L) {
    size_t e4 = ((size_t)blockIdx.x * 256 + threadIdx.x) * 4;
    float4 v = *(const float4*)(src + e4);
    bf16 h, l; __nv_bfloat162 h01, h23, l01, l23;
    bsplit(v.x, h, l); h01.x = h; l01.x = l;
    bsplit(v.y, h, l); h01.y = h; l01.y = l;
    bsplit(v.z, h, l); h23.x = h; l23.x = l;
    bsplit(v.w, h, l); h23.y = h; l23.y = l;
    *(__nv_bfloat162*)(H + e4) = h01; *(__nv_bfloat162*)(H + e4 + 2) = h23;
    *(__nv_bfloat162*)(L + e4) = l01; *(__nv_bfloat162*)(L + e4 + 2) = l23;
}

__global__ void k_wcomb_split(const float* __restrict__ W1, const float* __restrict__ W2) {
    int i = blockIdx.x * 256 + threadIdx.x;
    if (i >= Hn * Dn) return;
    int hh = i >> 8, d = i & (Dn - 1);
    const float* w1 = W1 + (size_t)hh * 4 * Dn;
    const float* w2 = W2 + (size_t)hh * 4 * Dn;
    float v; bf16 h, l;
    size_t base = (size_t)hh * 3 * Dn + d;
    v = w1[d] + w1[2 * Dn + d];      bsplit(v, h, l); g_W1H[base] = h;          g_W1L[base] = l;
    v = w1[Dn + d] - w1[2 * Dn + d]; bsplit(v, h, l); g_W1H[base + Dn] = h;     g_W1L[base + Dn] = l;
    v = w1[3 * Dn + d];              bsplit(v, h, l); g_W1H[base + 2 * Dn] = h; g_W1L[base + 2 * Dn] = l;
    v = w2[d] + w2[2 * Dn + d];      bsplit(v, h, l); g_W2H[base] = h;          g_W2L[base] = l;
    v = w2[Dn + d] - w2[2 * Dn + d]; bsplit(v, h, l); g_W2H[base + Dn] = h;     g_W2L[base + Dn] = l;
    v = w2[3 * Dn + d];              bsplit(v, h, l); g_W2H[base + 2 * Dn] = h; g_W2L[base + 2 * Dn] = l;
}

// ============================================================================
extern "C" void kernel_launch(void* const* d_in, const int* in_sizes, int n_in,
                              void* d_out, int out_size) {
    const float* cs = (const float*)d_in[0];
    const float* rs = (const float*)d_in[1];
    const float* W1 = (const float*)d_in[2];
    const float* b1 = (const float*)d_in[3];
    const float* W2 = (const float*)d_in[4];
    const float* b2 = (const float*)d_in[5];
    float* cl = (float*)d_out;
    float* rl = cl + (size_t)MC * Hn;

    bf16 *eH, *eL, *csH, *csL, *rsH, *rsL;
    bf16 *cdH, *cdL, *pcH, *pcL, *rdH, *rdL, *prH, *prL, *w1H, *w1L, *w2H, *w2L;
    cudaGetSymbolAddress((void**)&eH, g_EH);   cudaGetSymbolAddress((void**)&eL, g_EL);
    cudaGetSymbolAddress((void**)&csH, g_csH); cudaGetSymbolAddress((void**)&csL, g_csL);
    cudaGetSymbolAddress((void**)&rsH, g_rsH); cudaGetSymbolAddress((void**)&rsL, g_rsL);
    cudaGetSymbolAddress((void**)&cdH, g_cdH); cudaGetSymbolAddress((void**)&cdL, g_cdL);
    cudaGetSymbolAddress((void**)&pcH, g_pcH); cudaGetSymbolAddress((void**)&pcL, g_pcL);
    cudaGetSymbolAddress((void**)&rdH, g_rdH); cudaGetSymbolAddress((void**)&rdL, g_rdL);
    cudaGetSymbolAddress((void**)&prH, g_prH); cudaGetSymbolAddress((void**)&prL, g_prL);
    cudaGetSymbolAddress((void**)&w1H, g_W1H); cudaGetSymbolAddress((void**)&w1L, g_W1L);
    cudaGetSymbolAddress((void**)&w2H, g_W2H); cudaGetSymbolAddress((void**)&w2L, g_W2L);
    float *gas, *gbs, *prS, *pcS;
    cudaGetSymbolAddress((void**)&gas, g_asum);
    cudaGetSymbolAddress((void**)&gbs, g_bsum);
    cudaGetSymbolAddress((void**)&prS, g_prS); cudaGetSymbolAddress((void**)&pcS, g_pcS);

    cudaFuncSetAttribute(k_gemm<0,0,0>, cudaFuncAttributeMaxDynamicSharedMemorySize, SMEM_DYN);
    cudaFuncSetAttribute(k_gemm<1,0,1>, cudaFuncAttributeMaxDynamicSharedMemorySize, SMEM_DYN);
    cudaFuncSetAttribute(k_gemm<1,1,1>, cudaFuncAttributeMaxDynamicSharedMemorySize, SMEM_DYN);
    cudaFuncSetAttribute(k_gemm<2,0,0>, cudaFuncAttributeMaxDynamicSharedMemorySize, SMEM_DYN);

    k_wcomb_split<<<(Hn * Dn + 255) / 256, 256>>>(W1, W2);
    k_split<<<(int)((size_t)MC * Dn / 1024), 256>>>(cs, csH, csL);
    k_split<<<(int)((size_t)MR * Dn / 1024), 256>>>(rs, rsH, rsL);

    // GEMM0: exp(cs*rs^T - 64) split pairs + partial sums
    k_gemm<0,0,0><<<dim3(16, 4, Bn), 128, SMEM_DYN>>>(
        csH, csL, csH, csL, csH, csL, rsH, rsL,
        nullptr, nullptr, nullptr, nullptr, eH, eL, nullptr, nullptr,
        prS, pcS,
        Dn, Dn, Dn, LRn,
        (size_t)LCn * Dn, (size_t)LRn * Dn, (size_t)LCn * LRn, 0);

    k_merge_both<<<(MC + MR) / 256, 256>>>();

    // cd: A = Ê row-major (K=512), B = rs[k][n] via trans-ldmatrix; scale 1/asum
    k_gemm<1,0,1><<<dim3(16, 2, Bn), 128, SMEM_DYN>>>(
        eH, eL, eH, eL, eH, eL, rsH, rsL,
        gas, cs, nullptr, nullptr, cdH, cdL, pcH, pcL,
        nullptr, nullptr,
        LRn, LRn, Dn, Dn,
        (size_t)LCn * LRn, (size_t)LRn * Dn, (size_t)LCn * Dn, LCn);

    // rd: A = Ê^T via trans-ldmatrix (K=2048), B = cs[k][n] via trans-ldmatrix
    k_gemm<1,1,1><<<dim3(4, 2, Bn), 128, SMEM_DYN>>>(
        eH, eL, eH, eL, eH, eL, csH, csL,
        gbs, rs, nullptr, nullptr, rdH, rdL, prH, prL,
        nullptr, nullptr,
        LCn, LRn, Dn, Dn,
        (size_t)LCn * LRn, (size_t)LCn * Dn, (size_t)LRn * Dn, LRn);

    // cl = relu([cs|cd|cs*cd] * W1c^T + b1)
    k_gemm<2,0,0><<<dim3(MC / 128, 1, 1), 128, SMEM_DYN>>>(
        csH, csL, cdH, cdL, pcH, pcL, w1H, w1L,
        nullptr, nullptr, b1, cl, nullptr, nullptr, nullptr, nullptr,
        nullptr, nullptr,
        3 * Dn, Dn, 3 * Dn, Hn, 0, 0, 0, 0);

    // rl = relu([rs|rd|rs*rd] * W2c^T + b2)
    k_gemm<2,0,0><<<dim3(MR / 128, 1, 1), 128, SMEM_DYN>>>(
        rsH, rsL, rdH, rdL, prH, prL, w2H, w2L,
        nullptr, nullptr, b2, rl, nullptr, nullptr, nullptr, nullptr,
        nullptr, nullptr,
        3 * Dn, Dn, 3 * Dn, Hn, 0, 0, 0, 0);
}